// round 5
// baseline (speedup 1.0000x reference)
#include <cuda_runtime.h>
#include <cuda_bf16.h>
#include <math.h>
#include <stdint.h>

// ---------------- problem constants ----------------
#define B_SZ   8192
#define XCOLS  145
#define IN_F   16
#define LAT    128
#define HID    1024
#define CS     6540     // (M+2)*K
#define CSP    6656     // CS padded to 256
#define MK     6528     // M*K
#define MK5    5440     // compacted (drop k%6==3, v==0)
#define MK5P   5632     // padded to 256

// ---------------- scratch (zero-initialized device globals) -----------------
__device__ __nv_bfloat16 g_h1hi[(size_t)B_SZ * HID];
__device__ __nv_bfloat16 g_h1lo[(size_t)B_SZ * HID];
__device__ float         g_h2f [(size_t)B_SZ * CS];
__device__ __nv_bfloat16 g_h2hi[(size_t)B_SZ * CSP];   // pads stay zero
__device__ __nv_bfloat16 g_h2lo[(size_t)B_SZ * CSP];
__device__ __nv_bfloat16 g_w2thi[(size_t)CSP * HID];   // W2^T, pad rows zero
__device__ __nv_bfloat16 g_w2tlo[(size_t)CSP * HID];
__device__ __nv_bfloat16 g_w3thi[(size_t)MK5P * CSP];  // W3^T compact, pads zero
__device__ __nv_bfloat16 g_w3tlo[(size_t)MK5P * CSP];
__device__ float         g_cc  [(size_t)B_SZ * MK5];
__device__ float         g_v5  [(size_t)B_SZ * 5];

// ---------------- low-level helpers ----------------
__device__ __forceinline__ uint32_t smem_u32(const void* p) {
    uint32_t a;
    asm("{ .reg .u64 t; cvta.to.shared.u64 t, %1; cvt.u32.u64 %0, t; }" : "=r"(a) : "l"(p));
    return a;
}
__device__ __forceinline__ void cpa16(uint32_t dst, const void* src) {
    asm volatile("cp.async.cg.shared.global [%0], [%1], 16;" :: "r"(dst), "l"(src));
}
#define CP_COMMIT() asm volatile("cp.async.commit_group;" ::: "memory")
#define CP_WAIT2()  asm volatile("cp.async.wait_group 2;" ::: "memory")

__device__ __forceinline__ void ldsm4(uint32_t& r0, uint32_t& r1, uint32_t& r2, uint32_t& r3,
                                      uint32_t addr) {
    asm volatile("ldmatrix.sync.aligned.m8n8.x4.shared.b16 {%0,%1,%2,%3}, [%4];"
                 : "=r"(r0), "=r"(r1), "=r"(r2), "=r"(r3) : "r"(addr));
}
__device__ __forceinline__ void mma_bf16(float* c, const uint32_t* a, uint32_t b0, uint32_t b1) {
    asm volatile(
        "mma.sync.aligned.m16n8k16.row.col.f32.bf16.bf16.f32 "
        "{%0,%1,%2,%3}, {%4,%5,%6,%7}, {%8,%9}, {%0,%1,%2,%3};"
        : "+f"(c[0]), "+f"(c[1]), "+f"(c[2]), "+f"(c[3])
        : "r"(a[0]), "r"(a[1]), "r"(a[2]), "r"(a[3]), "r"(b0), "r"(b1));
}

// ---------------- pipelined bf16x3 GEMM ----------------
// C(128x256 per CTA) = epi( (Ahi+Alo) @ (Bhi+Blo)^T )  via hi*hi + hi*lo + lo*hi
// smem stage: Ahi[128x32] Alo Bhi[256x32] Blo, 80B row stride
#define ROWB    80
#define A_LO_OFF 10240
#define B_HI_OFF 20480
#define B_LO_OFF 40960
#define STG_BYTES 61440
#define GEMM_SMEM (3 * STG_BYTES)

__global__ __launch_bounds__(512, 1)
void mma_gemm(const __nv_bfloat16* __restrict__ Ahi, const __nv_bfloat16* __restrict__ Alo, int lda,
              const __nv_bfloat16* __restrict__ Bhi, const __nv_bfloat16* __restrict__ Blo, int ldb,
              int nk,
              const float* __restrict__ bias, const float* __restrict__ v5,
              float* __restrict__ outf, __nv_bfloat16* __restrict__ outHi,
              __nv_bfloat16* __restrict__ outLo, int ldf, int ldhl,
              int Nlimit, int mode)
{
    extern __shared__ char smem[];
    const uint32_t sbase = smem_u32(smem);
    const int tid  = threadIdx.x;
    const int lane = tid & 31;
    const int wid  = tid >> 5;
    const int warp_m = wid & 3;
    const int warp_n = wid >> 2;
    const int bm = blockIdx.y * 128;
    const int bn = blockIdx.x * 256;

    // per-thread load lanes (A: 128 rows x 4 x 16B; B: 256 rows x 4 x 16B)
    const int lrow = tid >> 2;      // 0..127
    const int lchk = tid & 3;       // 0..3
    const char* aHiSrc = (const char*)(Ahi + (size_t)(bm + lrow) * lda + lchk * 8);
    const char* aLoSrc = (const char*)(Alo + (size_t)(bm + lrow) * lda + lchk * 8);
    const char* bHiSrc0 = (const char*)(Bhi + (size_t)(bn + lrow) * ldb + lchk * 8);
    const char* bLoSrc0 = (const char*)(Blo + (size_t)(bn + lrow) * ldb + lchk * 8);
    const char* bHiSrc1 = (const char*)(Bhi + (size_t)(bn + 128 + lrow) * ldb + lchk * 8);
    const char* bLoSrc1 = (const char*)(Blo + (size_t)(bn + 128 + lrow) * ldb + lchk * 8);
    const uint32_t dA  = lrow * ROWB + lchk * 16;
    const uint32_t dB0 = dA;
    const uint32_t dB1 = dA + 128 * ROWB;

    float acc[2][8][4];
    #pragma unroll
    for (int i = 0; i < 2; ++i)
        #pragma unroll
        for (int j = 0; j < 8; ++j)
            #pragma unroll
            for (int l = 0; l < 4; ++l) acc[i][j][l] = 0.f;

    auto load_stage = [&](int s, int kc) {
        const uint32_t sA = sbase + s * STG_BYTES;
        const size_t kb = (size_t)kc * 64;     // 32 bf16 = 64 bytes per chunk
        cpa16(sA + dA, aHiSrc + kb);
        cpa16(sA + A_LO_OFF + dA, aLoSrc + kb);
        cpa16(sA + B_HI_OFF + dB0, bHiSrc0 + kb);
        cpa16(sA + B_HI_OFF + dB1, bHiSrc1 + kb);
        cpa16(sA + B_LO_OFF + dB0, bLoSrc0 + kb);
        cpa16(sA + B_LO_OFF + dB1, bLoSrc1 + kb);
    };

    // prologue: stages 0,1
    load_stage(0, 0); CP_COMMIT();
    if (nk > 1) load_stage(1, 1);
    CP_COMMIT();

    const int l15  = lane & 15;
    const int lksl = (lane >> 4) & 1;

    for (int k = 0; k < nk; ++k) {
        const int fetch = k + 2;
        if (fetch < nk) load_stage(fetch % 3, fetch);
        CP_COMMIT();
        CP_WAIT2();
        __syncthreads();

        const uint32_t sA = sbase + (k % 3) * STG_BYTES;
        const uint32_t sB = sA + B_HI_OFF;

        #pragma unroll
        for (int ks = 0; ks < 2; ++ks) {
            const uint32_t koff = ks * 32 + lksl * 16;
            uint32_t ahi[2][4], alo[2][4];
            #pragma unroll
            for (int mt = 0; mt < 2; ++mt) {
                uint32_t ra = sA + (uint32_t)(warp_m * 32 + mt * 16 + l15) * ROWB + koff;
                ldsm4(ahi[mt][0], ahi[mt][1], ahi[mt][2], ahi[mt][3], ra);
                ldsm4(alo[mt][0], alo[mt][1], alo[mt][2], alo[mt][3], ra + A_LO_OFF);
            }
            // B fragments: double-buffered across g (prefetch g+1 during g's MMAs)
            uint32_t bh[2][4], bl[2][4];
            {
                uint32_t rb = sB + (uint32_t)(warp_n * 64 + l15) * ROWB + koff;
                ldsm4(bh[0][0], bh[0][1], bh[0][2], bh[0][3], rb);
                ldsm4(bl[0][0], bl[0][1], bl[0][2], bl[0][3], rb + (B_LO_OFF - B_HI_OFF));
            }
            #pragma unroll
            for (int g = 0; g < 4; ++g) {
                const int cur = g & 1, nxt = cur ^ 1;
                if (g < 3) {
                    uint32_t rb = sB + (uint32_t)(warp_n * 64 + (g + 1) * 16 + l15) * ROWB + koff;
                    ldsm4(bh[nxt][0], bh[nxt][1], bh[nxt][2], bh[nxt][3], rb);
                    ldsm4(bl[nxt][0], bl[nxt][1], bl[nxt][2], bl[nxt][3],
                          rb + (B_LO_OFF - B_HI_OFF));
                }
                float* c00 = acc[0][2 * g];
                float* c01 = acc[0][2 * g + 1];
                float* c10 = acc[1][2 * g];
                float* c11 = acc[1][2 * g + 1];
                // pass-major order: same accumulator revisited at distance 4
                mma_bf16(c00, ahi[0], bh[cur][0], bh[cur][2]);
                mma_bf16(c01, ahi[0], bh[cur][1], bh[cur][3]);
                mma_bf16(c10, ahi[1], bh[cur][0], bh[cur][2]);
                mma_bf16(c11, ahi[1], bh[cur][1], bh[cur][3]);
                mma_bf16(c00, ahi[0], bl[cur][0], bl[cur][2]);
                mma_bf16(c01, ahi[0], bl[cur][1], bl[cur][3]);
                mma_bf16(c10, ahi[1], bl[cur][0], bl[cur][2]);
                mma_bf16(c11, ahi[1], bl[cur][1], bl[cur][3]);
                mma_bf16(c00, alo[0], bh[cur][0], bh[cur][2]);
                mma_bf16(c01, alo[0], bh[cur][1], bh[cur][3]);
                mma_bf16(c10, alo[1], bh[cur][0], bh[cur][2]);
                mma_bf16(c11, alo[1], bh[cur][1], bh[cur][3]);
            }
        }
        __syncthreads();
    }

    // ---------------- epilogue ----------------
    #pragma unroll
    for (int mt = 0; mt < 2; ++mt) {
        #pragma unroll
        for (int h = 0; h < 2; ++h) {
            const int row = bm + warp_m * 32 + mt * 16 + (lane >> 2) + h * 8;
            #pragma unroll
            for (int nt = 0; nt < 8; ++nt) {
                const int col = bn + warp_n * 64 + nt * 8 + ((lane & 3) << 1);
                float v0 = acc[mt][nt][h * 2 + 0];
                float v1 = acc[mt][nt][h * 2 + 1];
                if (mode == 1) {
                    if (col < Nlimit) {
                        float t0 = tanhf(v0 + bias[col]);
                        float t1 = tanhf(v1 + bias[col + 1]);
                        *reinterpret_cast<float2*>(outf + (size_t)row * ldf + col) =
                            make_float2(t0, t1);
                        __nv_bfloat16 h0 = __float2bfloat16(t0);
                        __nv_bfloat16 h1 = __float2bfloat16(t1);
                        __nv_bfloat162 hp; hp.x = h0; hp.y = h1;
                        __nv_bfloat162 lp;
                        lp.x = __float2bfloat16(t0 - __bfloat162float(h0));
                        lp.y = __float2bfloat16(t1 - __bfloat162float(h1));
                        *reinterpret_cast<__nv_bfloat162*>(outHi + (size_t)row * ldhl + col) = hp;
                        *reinterpret_cast<__nv_bfloat162*>(outLo + (size_t)row * ldhl + col) = lp;
                    }
                } else {
                    #pragma unroll
                    for (int e = 0; e < 2; ++e) {
                        int c = col + e;
                        if (c < Nlimit) {
                            float val = (e == 0) ? v0 : v1;
                            int m6 = c / 5, j5 = c - m6 * 5;
                            int kk = (j5 < 3) ? j5 : j5 + 1;
                            float sc = v5[(size_t)row * 5 + j5];
                            outf[(size_t)row * ldf + c] = (val + bias[m6 * 6 + kk]) * sc;
                        }
                    }
                }
            }
        }
    }
}

// ---------------- transpose + bf16 split (optionally compact k%6==3) --------
__global__ __launch_bounds__(256)
void transpose_split(const float* __restrict__ W, int R, int Cstride, int nlimit,
                     __nv_bfloat16* __restrict__ Thi, __nv_bfloat16* __restrict__ Tlo,
                     int ldt, int compact)
{
    __shared__ float ts[32][33];
    const int tx = threadIdx.x, ty = threadIdx.y;   // 32 x 8
    const int n0 = blockIdx.x * 32, k0 = blockIdx.y * 32;
    #pragma unroll
    for (int i = 0; i < 32; i += 8) {
        int k = k0 + ty + i, n = n0 + tx;
        ts[ty + i][tx] = (k < R && n < nlimit) ? W[(size_t)k * Cstride + n] : 0.f;
    }
    __syncthreads();
    #pragma unroll
    for (int i = 0; i < 32; i += 8) {
        int n = n0 + ty + i, k = k0 + tx;
        if (n < nlimit && k < R) {
            int np = n;
            if (compact) {
                int r6 = n % 6;
                if (r6 == 3) continue;
                np = (n / 6) * 5 + (r6 < 3 ? r6 : r6 - 1);
            }
            float val = ts[tx][ty + i];
            __nv_bfloat16 hi = __float2bfloat16(val);
            float lo = val - __bfloat162float(hi);
            Thi[(size_t)np * ldt + k] = hi;
            Tlo[(size_t)np * ldt + k] = __float2bfloat16(lo);
        }
    }
}

// ---------------- h1 = tanh(z @ W1 + b1), SIMT (tiny) ----------------------
__global__ __launch_bounds__(256, 2)
void h1_kernel(const float* __restrict__ A, int lda,
               const float* __restrict__ Bm, int ldb,
               const float* __restrict__ bias,
               __nv_bfloat16* __restrict__ outHi, __nv_bfloat16* __restrict__ outLo)
{
    __shared__ float As[16][128 + 4];
    __shared__ float Bs[16][128 + 4];
    const int tid = threadIdx.x;
    const int bm = blockIdx.y * 128, bn = blockIdx.x * 128;
    const int tx = tid % 16, ty = tid / 16;
    float acc[8][8];
    #pragma unroll
    for (int i = 0; i < 8; ++i)
        #pragma unroll
        for (int j = 0; j < 8; ++j) acc[i][j] = 0.f;

    for (int k0 = 0; k0 < LAT; k0 += 16) {
        #pragma unroll
        for (int i = 0; i < 8; ++i) {
            int idx = tid + i * 256;
            int m = idx / 16, k = idx % 16;
            As[k][m] = A[(size_t)(bm + m) * lda + k0 + k];
        }
        #pragma unroll
        for (int i = 0; i < 8; ++i) {
            int idx = tid + i * 256;
            int k = idx / 128, n = idx % 128;
            Bs[k][n] = Bm[(size_t)(k0 + k) * ldb + bn + n];
        }
        __syncthreads();
        #pragma unroll
        for (int k = 0; k < 16; ++k) {
            float ra[8], rb[8];
            #pragma unroll
            for (int i = 0; i < 8; ++i) ra[i] = As[k][ty * 8 + i];
            #pragma unroll
            for (int j = 0; j < 8; ++j) rb[j] = Bs[k][tx * 8 + j];
            #pragma unroll
            for (int i = 0; i < 8; ++i)
                #pragma unroll
                for (int j = 0; j < 8; ++j) acc[i][j] = fmaf(ra[i], rb[j], acc[i][j]);
        }
        __syncthreads();
    }
    #pragma unroll
    for (int i = 0; i < 8; ++i) {
        int row = bm + ty * 8 + i;
        #pragma unroll
        for (int j = 0; j < 8; ++j) {
            int col = bn + tx * 8 + j;
            float t = tanhf(acc[i][j] + bias[col]);
            __nv_bfloat16 hi = __float2bfloat16(t);
            float lo = t - __bfloat162float(hi);
            size_t o = (size_t)row * HID + col;
            outHi[o] = hi;
            outLo[o] = __float2bfloat16(lo);
        }
    }
}

// ---------------- tail: 12 dot products -> v5 -------------------------------
__global__ __launch_bounds__(128)
void tail_v_kernel(const float* __restrict__ h2,
                   const float* __restrict__ W3,
                   const float* __restrict__ b3,
                   const float* __restrict__ x,
                   float* __restrict__ v5)
{
    const int b = blockIdx.x;
    const int t = threadIdx.x;
    float p[12];
    #pragma unroll
    for (int j = 0; j < 12; ++j) p[j] = 0.f;
    const float* hrow = h2 + (size_t)b * CS;
    for (int c = t; c < CS; c += 128) {
        float hv = hrow[c];
        const float* wr = W3 + (size_t)c * CS + MK;
        #pragma unroll
        for (int j = 0; j < 12; ++j) p[j] = fmaf(hv, wr[j], p[j]);
    }
    __shared__ float red[128];
    __shared__ float dtail[12];
    for (int j = 0; j < 12; ++j) {
        red[t] = p[j];
        __syncthreads();
        for (int s = 64; s > 0; s >>= 1) {
            if (t < s) red[t] += red[t + s];
            __syncthreads();
        }
        if (t == 0) dtail[j] = red[0] + b3[MK + j];
        __syncthreads();
    }
    if (t < 5) {
        int k = (t < 3) ? t : t + 1;
        float s = x[(size_t)(B_SZ - 1) * XCOLS + IN_F];
        float sv = fmaf(s, dtail[k], dtail[k + 6]);
        float r = (k < 3) ? cosf(sv * (float)k) : sinf(sv * (float)(k - 3));
        v5[(size_t)b * 5 + t] = r;
    }
}

// ---------------- final: group-of-5 sums + 16->64 adaptive linear -----------
__global__ __launch_bounds__(256)
void final_kernel(const float* __restrict__ cc,
                  const float* __restrict__ x,
                  float* __restrict__ out)
{
    const int b = blockIdx.x;
    const int t = threadIdx.x;
    __shared__ float row[MK5];
    __shared__ float inp[IN_F];
    const float* src = cc + (size_t)b * MK5;
    for (int i = t; i < MK5; i += 256) row[i] = src[i];
    if (t < IN_F) inp[t] = x[(size_t)b * XCOLS + t];
    __syncthreads();
    if (t < 64) {
        const int o = t;
        float accum = 0.f;
        #pragma unroll
        for (int i = 0; i < IN_F; ++i) {
            const float* g = row + (i * 64 + o) * 5;
            float wsum = ((g[0] + g[1]) + (g[2] + g[3])) + g[4];
            accum = fmaf(inp[i], wsum, accum);
        }
        const float* g = row + (1024 + o) * 5;
        accum += ((g[0] + g[1]) + (g[2] + g[3])) + g[4];
        out[(size_t)b * 64 + o] = accum;
    }
}

// ----------------------------- launch ---------------------------------------
extern "C" void kernel_launch(void* const* d_in, const int* in_sizes, int n_in,
                              void* d_out, int out_size)
{
    const float* x  = (const float*)d_in[0];
    const float* W1 = (const float*)d_in[1];
    const float* b1 = (const float*)d_in[2];
    const float* W2 = (const float*)d_in[3];
    const float* b2 = (const float*)d_in[4];
    const float* W3 = (const float*)d_in[5];
    const float* b3 = (const float*)d_in[6];
    float* out = (float*)d_out;

    __nv_bfloat16 *h1hi, *h1lo, *h2hi, *h2lo, *w2thi, *w2tlo, *w3thi, *w3tlo;
    float *h2f, *cc, *v5;
    cudaGetSymbolAddress((void**)&h1hi, g_h1hi);
    cudaGetSymbolAddress((void**)&h1lo, g_h1lo);
    cudaGetSymbolAddress((void**)&h2f,  g_h2f);
    cudaGetSymbolAddress((void**)&h2hi, g_h2hi);
    cudaGetSymbolAddress((void**)&h2lo, g_h2lo);
    cudaGetSymbolAddress((void**)&w2thi, g_w2thi);
    cudaGetSymbolAddress((void**)&w2tlo, g_w2tlo);
    cudaGetSymbolAddress((void**)&w3thi, g_w3thi);
    cudaGetSymbolAddress((void**)&w3tlo, g_w3tlo);
    cudaGetSymbolAddress((void**)&cc,  g_cc);
    cudaGetSymbolAddress((void**)&v5,  g_v5);

    static bool attr_set = false;
    if (!attr_set) {
        cudaFuncSetAttribute(mma_gemm, cudaFuncAttributeMaxDynamicSharedMemorySize, GEMM_SMEM);
        attr_set = true;
    }

    // 0a) W2^T split: [1024][6540] -> [6540][1024] (pad rows stay zero)
    transpose_split<<<dim3((CS + 31) / 32, (HID + 31) / 32), dim3(32, 8)>>>(
        W2, HID, CS, CS, w2thi, w2tlo, HID, 0);
    // 0b) W3^T split + compact: [6540][6528] -> [5440][6656-ld]
    transpose_split<<<dim3((MK + 31) / 32, (CS + 31) / 32), dim3(32, 8)>>>(
        W3, CS, CS, MK, w3thi, w3tlo, CSP, 1);

    // 1) h1 = tanh(z @ W1 + b1) -> bf16 hi/lo
    h1_kernel<<<dim3(HID / 128, B_SZ / 128), 256>>>(
        x + (IN_F + 1), XCOLS, W1, HID, b1, h1hi, h1lo);

    // 2) h2 = tanh(h1 @ W2 + b2): bf16x3 HMMA, K=1024, N covers 6656
    mma_gemm<<<dim3(CSP / 256, B_SZ / 128), 512, GEMM_SMEM>>>(
        h1hi, h1lo, HID, w2thi, w2tlo, HID, HID / 32,
        b2, nullptr, h2f, h2hi, h2lo, CS, CSP, CS, 1);

    // 3) tail 12 columns -> v5
    tail_v_kernel<<<B_SZ, 128>>>(h2f, W3, b3, x, v5);

    // 4) big GEMM: cc = (h2 @ W3t' + b3) * v5 : K covers 6560, N covers 5632
    mma_gemm<<<dim3(MK5P / 256, B_SZ / 128), 512, GEMM_SMEM>>>(
        h2hi, h2lo, CSP, w3thi, w3tlo, CSP, (CS + 31) / 32,
        b3, v5, cc, nullptr, nullptr, MK5, 0,
        MK5, 2);

    // 5) group-of-5 sums + adaptive linear
    final_kernel<<<B_SZ, 256>>>(cc, x, out);
}

// round 6
// speedup vs baseline: 1.9677x; 1.9677x over previous
#include <cuda_runtime.h>
#include <cuda_fp16.h>
#include <math.h>
#include <stdint.h>

// ---------------- problem constants ----------------
#define B_SZ   8192
#define XCOLS  145
#define IN_F   16
#define LAT    128
#define HID    1024
#define CS     6540     // (M+2)*K
#define CSP    6656     // CS padded to 256
#define MK     6528     // M*K
#define MK5    5440     // compacted (drop k%6==3, v==0)
#define MK5P   5632     // padded to 256

// ---------------- scratch (zero-initialized device globals) -----------------
__device__ __half g_h1hi[(size_t)B_SZ * HID];
__device__ __half g_h1lo[(size_t)B_SZ * HID];
__device__ float  g_h2f [(size_t)B_SZ * CS];
__device__ __half g_h2h [(size_t)B_SZ * CSP];     // pads stay zero
__device__ __half g_w2th[(size_t)CSP * HID];      // W2^T hi, pad rows zero
__device__ __half g_w3th[(size_t)MK5P * CSP];     // W3^T compact, pads zero
__device__ float  g_cc  [(size_t)B_SZ * MK5];
__device__ float  g_v5  [(size_t)B_SZ * 5];

// ---------------- low-level helpers ----------------
__device__ __forceinline__ uint32_t smem_u32(const void* p) {
    uint32_t a;
    asm("{ .reg .u64 t; cvta.to.shared.u64 t, %1; cvt.u32.u64 %0, t; }" : "=r"(a) : "l"(p));
    return a;
}
__device__ __forceinline__ void cpa16(uint32_t dst, const void* src) {
    asm volatile("cp.async.cg.shared.global [%0], [%1], 16;" :: "r"(dst), "l"(src));
}
#define CP_COMMIT() asm volatile("cp.async.commit_group;" ::: "memory")
#define CP_WAIT2()  asm volatile("cp.async.wait_group 2;" ::: "memory")
#define CP_WAIT3()  asm volatile("cp.async.wait_group 3;" ::: "memory")

__device__ __forceinline__ void ldsm4(uint32_t& r0, uint32_t& r1, uint32_t& r2, uint32_t& r3,
                                      uint32_t addr) {
    asm volatile("ldmatrix.sync.aligned.m8n8.x4.shared.b16 {%0,%1,%2,%3}, [%4];"
                 : "=r"(r0), "=r"(r1), "=r"(r2), "=r"(r3) : "r"(addr));
}
__device__ __forceinline__ void mma_f16(float* c, const uint32_t* a, uint32_t b0, uint32_t b1) {
    asm volatile(
        "mma.sync.aligned.m16n8k16.row.col.f32.f16.f16.f32 "
        "{%0,%1,%2,%3}, {%4,%5,%6,%7}, {%8,%9}, {%0,%1,%2,%3};"
        : "+f"(c[0]), "+f"(c[1]), "+f"(c[2]), "+f"(c[3])
        : "r"(a[0]), "r"(a[1]), "r"(a[2]), "r"(a[3]), "r"(b0), "r"(b1));
}

// ============================================================================
// GEMM A: 2-pass fp16 (A hi/lo x B hi), tile 128x256, BK=32, 3-stage.
// h2 = tanh(h1 @ W2t^T + b2) -> h2f (fp32) + h2h (fp16)
// ============================================================================
#define ROWB2    80
#define A_LO_OFF 10240
#define B_HI_OFF 20480
#define STG2     40960
#define GEMM2_SMEM (3 * STG2)

__global__ __launch_bounds__(512, 1)
void gemm_h2(const __half* __restrict__ Ahi, const __half* __restrict__ Alo,
             const __half* __restrict__ Bh,
             const float* __restrict__ bias,
             float* __restrict__ outf, __half* __restrict__ outh)
{
    extern __shared__ char smem[];
    const uint32_t sbase = smem_u32(smem);
    const int tid  = threadIdx.x;
    const int lane = tid & 31;
    const int wid  = tid >> 5;
    const int warp_m = wid & 3;
    const int warp_n = wid >> 2;
    const int bm = blockIdx.y * 128;
    const int bn = blockIdx.x * 256;

    const int lrow = tid >> 2;
    const int lchk = tid & 3;
    const char* aHiSrc = (const char*)(Ahi + (size_t)(bm + lrow) * HID + lchk * 8);
    const char* aLoSrc = (const char*)(Alo + (size_t)(bm + lrow) * HID + lchk * 8);
    const char* bSrc0  = (const char*)(Bh + (size_t)(bn + lrow) * HID + lchk * 8);
    const char* bSrc1  = (const char*)(Bh + (size_t)(bn + 128 + lrow) * HID + lchk * 8);
    const uint32_t dA  = lrow * ROWB2 + lchk * 16;
    const uint32_t dB1 = dA + 128 * ROWB2;

    float acc[2][8][4];
    #pragma unroll
    for (int i = 0; i < 2; ++i)
        #pragma unroll
        for (int j = 0; j < 8; ++j)
            #pragma unroll
            for (int l = 0; l < 4; ++l) acc[i][j][l] = 0.f;

    auto load_stage = [&](int s, int kc) {
        const uint32_t sA = sbase + s * STG2;
        const size_t kb = (size_t)kc * 64;     // 32 fp16 = 64B
        cpa16(sA + dA, aHiSrc + kb);
        cpa16(sA + A_LO_OFF + dA, aLoSrc + kb);
        cpa16(sA + B_HI_OFF + dA, bSrc0 + kb);
        cpa16(sA + B_HI_OFF + dB1, bSrc1 + kb);
    };

    const int nk = HID / 32;    // 32
    load_stage(0, 0); CP_COMMIT();
    load_stage(1, 1); CP_COMMIT();

    const int l15  = lane & 15;
    const int lksl = (lane >> 4) & 1;

    for (int k = 0; k < nk; ++k) {
        const int fetch = k + 2;
        if (fetch < nk) load_stage(fetch % 3, fetch);
        CP_COMMIT();
        CP_WAIT2();
        __syncthreads();

        const uint32_t sA = sbase + (k % 3) * STG2;
        const uint32_t sB = sA + B_HI_OFF;

        #pragma unroll
        for (int ks = 0; ks < 2; ++ks) {
            const uint32_t koff = ks * 32 + lksl * 16;
            uint32_t ahi[2][4], alo[2][4];
            #pragma unroll
            for (int mt = 0; mt < 2; ++mt) {
                uint32_t ra = sA + (uint32_t)(warp_m * 32 + mt * 16 + l15) * ROWB2 + koff;
                ldsm4(ahi[mt][0], ahi[mt][1], ahi[mt][2], ahi[mt][3], ra);
                ldsm4(alo[mt][0], alo[mt][1], alo[mt][2], alo[mt][3], ra + A_LO_OFF);
            }
            uint32_t bh[2][4];
            {
                uint32_t rb = sB + (uint32_t)(warp_n * 64 + l15) * ROWB2 + koff;
                ldsm4(bh[0][0], bh[0][1], bh[0][2], bh[0][3], rb);
            }
            #pragma unroll
            for (int g = 0; g < 4; ++g) {
                const int cur = g & 1, nxt = cur ^ 1;
                if (g < 3) {
                    uint32_t rb = sB + (uint32_t)(warp_n * 64 + (g + 1) * 16 + l15) * ROWB2 + koff;
                    ldsm4(bh[nxt][0], bh[nxt][1], bh[nxt][2], bh[nxt][3], rb);
                }
                float* c00 = acc[0][2 * g];
                float* c01 = acc[0][2 * g + 1];
                float* c10 = acc[1][2 * g];
                float* c11 = acc[1][2 * g + 1];
                mma_f16(c00, ahi[0], bh[cur][0], bh[cur][2]);
                mma_f16(c01, ahi[0], bh[cur][1], bh[cur][3]);
                mma_f16(c10, ahi[1], bh[cur][0], bh[cur][2]);
                mma_f16(c11, ahi[1], bh[cur][1], bh[cur][3]);
                mma_f16(c00, alo[0], bh[cur][0], bh[cur][2]);
                mma_f16(c01, alo[0], bh[cur][1], bh[cur][3]);
                mma_f16(c10, alo[1], bh[cur][0], bh[cur][2]);
                mma_f16(c11, alo[1], bh[cur][1], bh[cur][3]);
            }
        }
        __syncthreads();
    }

    // epilogue: tanh(+bias) -> fp32 out + fp16 out
    #pragma unroll
    for (int mt = 0; mt < 2; ++mt) {
        #pragma unroll
        for (int h = 0; h < 2; ++h) {
            const int row = bm + warp_m * 32 + mt * 16 + (lane >> 2) + h * 8;
            #pragma unroll
            for (int nt = 0; nt < 8; ++nt) {
                const int col = bn + warp_n * 64 + nt * 8 + ((lane & 3) << 1);
                if (col < CS) {
                    float t0 = tanhf(acc[mt][nt][h * 2 + 0] + bias[col]);
                    float t1 = tanhf(acc[mt][nt][h * 2 + 1] + bias[col + 1]);
                    *reinterpret_cast<float2*>(outf + (size_t)row * CS + col) =
                        make_float2(t0, t1);
                    __half2 hp;
                    hp.x = __float2half(t0);
                    hp.y = __float2half(t1);
                    *reinterpret_cast<__half2*>(outh + (size_t)row * CSP + col) = hp;
                }
            }
        }
    }
}

// ============================================================================
// GEMM B: 1-pass fp16, tile 128x256, BK=64, 4-stage (distance-3 prefetch).
// cc = (h2h @ W3t^T + b3[expand]) * v5
// ============================================================================
#define ROWB1    144                    // 128B data + 16B pad (conflict-free)
#define B1_OFF   (128 * ROWB1)          // 18432
#define STG1     (384 * ROWB1)          // 55296
#define GEMM1_SMEM (4 * STG1)           // 221184

__global__ __launch_bounds__(512, 1)
void gemm_cc(const __half* __restrict__ A, const __half* __restrict__ B,
             const float* __restrict__ bias, const float* __restrict__ v5,
             float* __restrict__ outf)
{
    extern __shared__ char smem[];
    const uint32_t sbase = smem_u32(smem);
    const int tid  = threadIdx.x;
    const int lane = tid & 31;
    const int wid  = tid >> 5;
    const int warp_m = wid & 3;
    const int warp_n = wid >> 2;
    const int bm = blockIdx.y * 128;
    const int bn = blockIdx.x * 256;

    const int lrow = tid >> 2;
    const int lchk = tid & 3;
    const char* aSrc  = (const char*)(A + (size_t)(bm + lrow) * CSP + lchk * 8);
    const char* bSrc0 = (const char*)(B + (size_t)(bn + lrow) * CSP + lchk * 8);
    const char* bSrc1 = (const char*)(B + (size_t)(bn + 128 + lrow) * CSP + lchk * 8);
    const uint32_t dA  = lrow * ROWB1 + lchk * 16;
    const uint32_t dB1 = dA + 128 * ROWB1;

    float acc[2][8][4];
    #pragma unroll
    for (int i = 0; i < 2; ++i)
        #pragma unroll
        for (int j = 0; j < 8; ++j)
            #pragma unroll
            for (int l = 0; l < 4; ++l) acc[i][j][l] = 0.f;

    auto load_stage = [&](int s, int kc) {
        const uint32_t sA = sbase + s * STG1;
        const size_t kb = (size_t)kc * 128;   // 64 fp16 = 128B
        cpa16(sA + dA, aSrc + kb);
        cpa16(sA + dA + 64, aSrc + kb + 64);
        cpa16(sA + B1_OFF + dA, bSrc0 + kb);
        cpa16(sA + B1_OFF + dA + 64, bSrc0 + kb + 64);
        cpa16(sA + B1_OFF + dB1, bSrc1 + kb);
        cpa16(sA + B1_OFF + dB1 + 64, bSrc1 + kb + 64);
    };

    const int nk = (CS + 63) / 64;   // 103, covers 6592 <= CSP (pads zero)
    load_stage(0, 0); CP_COMMIT();
    load_stage(1, 1); CP_COMMIT();
    load_stage(2, 2); CP_COMMIT();

    const int l15  = lane & 15;
    const int lksl = (lane >> 4) & 1;

    for (int k = 0; k < nk; ++k) {
        const int fetch = k + 3;
        if (fetch < nk) load_stage(fetch & 3, fetch);
        CP_COMMIT();
        CP_WAIT3();
        __syncthreads();

        const uint32_t sA = sbase + (k & 3) * STG1;
        const uint32_t sB = sA + B1_OFF;

        #pragma unroll
        for (int ks = 0; ks < 4; ++ks) {
            const uint32_t koff = ks * 32 + lksl * 16;
            uint32_t a[2][4];
            #pragma unroll
            for (int mt = 0; mt < 2; ++mt) {
                uint32_t ra = sA + (uint32_t)(warp_m * 32 + mt * 16 + l15) * ROWB1 + koff;
                ldsm4(a[mt][0], a[mt][1], a[mt][2], a[mt][3], ra);
            }
            uint32_t bh[2][4];
            {
                uint32_t rb = sB + (uint32_t)(warp_n * 64 + l15) * ROWB1 + koff;
                ldsm4(bh[0][0], bh[0][1], bh[0][2], bh[0][3], rb);
            }
            #pragma unroll
            for (int g = 0; g < 4; ++g) {
                const int cur = g & 1, nxt = cur ^ 1;
                if (g < 3) {
                    uint32_t rb = sB + (uint32_t)(warp_n * 64 + (g + 1) * 16 + l15) * ROWB1 + koff;
                    ldsm4(bh[nxt][0], bh[nxt][1], bh[nxt][2], bh[nxt][3], rb);
                }
                mma_f16(acc[0][2 * g],     a[0], bh[cur][0], bh[cur][2]);
                mma_f16(acc[0][2 * g + 1], a[0], bh[cur][1], bh[cur][3]);
                mma_f16(acc[1][2 * g],     a[1], bh[cur][0], bh[cur][2]);
                mma_f16(acc[1][2 * g + 1], a[1], bh[cur][1], bh[cur][3]);
            }
        }
        __syncthreads();
    }

    // epilogue: (+bias[expanded]) * v5
    #pragma unroll
    for (int mt = 0; mt < 2; ++mt) {
        #pragma unroll
        for (int h = 0; h < 2; ++h) {
            const int row = bm + warp_m * 32 + mt * 16 + (lane >> 2) + h * 8;
            #pragma unroll
            for (int nt = 0; nt < 8; ++nt) {
                const int col = bn + warp_n * 64 + nt * 8 + ((lane & 3) << 1);
                #pragma unroll
                for (int e = 0; e < 2; ++e) {
                    int c = col + e;
                    if (c < MK5) {
                        float val = acc[mt][nt][h * 2 + e];
                        int m6 = c / 5, j5 = c - m6 * 5;
                        int kk = (j5 < 3) ? j5 : j5 + 1;
                        float sc = v5[(size_t)row * 5 + j5];
                        outf[(size_t)row * MK5 + c] = (val + bias[m6 * 6 + kk]) * sc;
                    }
                }
            }
        }
    }
}

// ---------------- transpose + fp16 split (optionally compact k%6==3) --------
__global__ __launch_bounds__(256)
void transpose_h(const float* __restrict__ W, int R, int Cstride, int nlimit,
                 __half* __restrict__ Thi, int ldt, int compact)
{
    __shared__ float ts[32][33];
    const int tx = threadIdx.x, ty = threadIdx.y;   // 32 x 8
    const int n0 = blockIdx.x * 32, k0 = blockIdx.y * 32;
    #pragma unroll
    for (int i = 0; i < 32; i += 8) {
        int k = k0 + ty + i, n = n0 + tx;
        ts[ty + i][tx] = (k < R && n < nlimit) ? W[(size_t)k * Cstride + n] : 0.f;
    }
    __syncthreads();
    #pragma unroll
    for (int i = 0; i < 32; i += 8) {
        int n = n0 + ty + i, k = k0 + tx;
        if (n < nlimit && k < R) {
            int np = n;
            if (compact) {
                int r6 = n % 6;
                if (r6 == 3) continue;
                np = (n / 6) * 5 + (r6 < 3 ? r6 : r6 - 1);
            }
            Thi[(size_t)np * ldt + k] = __float2half(ts[tx][ty + i]);
        }
    }
}

// ---------------- h1 = tanh(z @ W1 + b1), SIMT -> fp16 hi/lo ----------------
__global__ __launch_bounds__(256, 2)
void h1_kernel(const float* __restrict__ A, int lda,
               const float* __restrict__ Bm, int ldb,
               const float* __restrict__ bias,
               __half* __restrict__ outHi, __half* __restrict__ outLo)
{
    __shared__ float As[16][128 + 4];
    __shared__ float Bs[16][128 + 4];
    const int tid = threadIdx.x;
    const int bm = blockIdx.y * 128, bn = blockIdx.x * 128;
    const int tx = tid % 16, ty = tid / 16;
    float acc[8][8];
    #pragma unroll
    for (int i = 0; i < 8; ++i)
        #pragma unroll
        for (int j = 0; j < 8; ++j) acc[i][j] = 0.f;

    for (int k0 = 0; k0 < LAT; k0 += 16) {
        #pragma unroll
        for (int i = 0; i < 8; ++i) {
            int idx = tid + i * 256;
            int m = idx / 16, k = idx % 16;
            As[k][m] = A[(size_t)(bm + m) * lda + k0 + k];
        }
        #pragma unroll
        for (int i = 0; i < 8; ++i) {
            int idx = tid + i * 256;
            int k = idx / 128, n = idx % 128;
            Bs[k][n] = Bm[(size_t)(k0 + k) * ldb + bn + n];
        }
        __syncthreads();
        #pragma unroll
        for (int k = 0; k < 16; ++k) {
            float ra[8], rb[8];
            #pragma unroll
            for (int i = 0; i < 8; ++i) ra[i] = As[k][ty * 8 + i];
            #pragma unroll
            for (int j = 0; j < 8; ++j) rb[j] = Bs[k][tx * 8 + j];
            #pragma unroll
            for (int i = 0; i < 8; ++i)
                #pragma unroll
                for (int j = 0; j < 8; ++j) acc[i][j] = fmaf(ra[i], rb[j], acc[i][j]);
        }
        __syncthreads();
    }
    #pragma unroll
    for (int i = 0; i < 8; ++i) {
        int row = bm + ty * 8 + i;
        #pragma unroll
        for (int j = 0; j < 8; ++j) {
            int col = bn + tx * 8 + j;
            float t = tanhf(acc[i][j] + bias[col]);
            __half hi = __float2half(t);
            size_t o = (size_t)row * HID + col;
            outHi[o] = hi;
            outLo[o] = __float2half(t - __half2float(hi));
        }
    }
}

// ---------------- tail: 12 dot products -> v5 -------------------------------
__global__ __launch_bounds__(128)
void tail_v_kernel(const float* __restrict__ h2,
                   const float* __restrict__ W3,
                   const float* __restrict__ b3,
                   const float* __restrict__ x,
                   float* __restrict__ v5)
{
    const int b = blockIdx.x;
    const int t = threadIdx.x;
    float p[12];
    #pragma unroll
    for (int j = 0; j < 12; ++j) p[j] = 0.f;
    const float* hrow = h2 + (size_t)b * CS;
    for (int c = t; c < CS; c += 128) {
        float hv = hrow[c];
        const float* wr = W3 + (size_t)c * CS + MK;
        #pragma unroll
        for (int j = 0; j < 12; ++j) p[j] = fmaf(hv, wr[j], p[j]);
    }
    __shared__ float red[128];
    __shared__ float dtail[12];
    for (int j = 0; j < 12; ++j) {
        red[t] = p[j];
        __syncthreads();
        for (int s = 64; s > 0; s >>= 1) {
            if (t < s) red[t] += red[t + s];
            __syncthreads();
        }
        if (t == 0) dtail[j] = red[0] + b3[MK + j];
        __syncthreads();
    }
    if (t < 5) {
        int k = (t < 3) ? t : t + 1;
        float s = x[(size_t)(B_SZ - 1) * XCOLS + IN_F];
        float sv = fmaf(s, dtail[k], dtail[k + 6]);
        float r = (k < 3) ? cosf(sv * (float)k) : sinf(sv * (float)(k - 3));
        v5[(size_t)b * 5 + t] = r;
    }
}

// ---------------- final: group-of-5 sums + 16->64 adaptive linear -----------
__global__ __launch_bounds__(256)
void final_kernel(const float* __restrict__ cc,
                  const float* __restrict__ x,
                  float* __restrict__ out)
{
    const int b = blockIdx.x;
    const int t = threadIdx.x;
    __shared__ float row[MK5];
    __shared__ float inp[IN_F];
    const float* src = cc + (size_t)b * MK5;
    for (int i = t; i < MK5; i += 256) row[i] = src[i];
    if (t < IN_F) inp[t] = x[(size_t)b * XCOLS + t];
    __syncthreads();
    if (t < 64) {
        const int o = t;
        float accum = 0.f;
        #pragma unroll
        for (int i = 0; i < IN_F; ++i) {
            const float* g = row + (i * 64 + o) * 5;
            float wsum = ((g[0] + g[1]) + (g[2] + g[3])) + g[4];
            accum = fmaf(inp[i], wsum, accum);
        }
        const float* g = row + (1024 + o) * 5;
        accum += ((g[0] + g[1]) + (g[2] + g[3])) + g[4];
        out[(size_t)b * 64 + o] = accum;
    }
}

// ----------------------------- launch ---------------------------------------
extern "C" void kernel_launch(void* const* d_in, const int* in_sizes, int n_in,
                              void* d_out, int out_size)
{
    const float* x  = (const float*)d_in[0];
    const float* W1 = (const float*)d_in[1];
    const float* b1 = (const float*)d_in[2];
    const float* W2 = (const float*)d_in[3];
    const float* b2 = (const float*)d_in[4];
    const float* W3 = (const float*)d_in[5];
    const float* b3 = (const float*)d_in[6];
    float* out = (float*)d_out;

    __half *h1hi, *h1lo, *h2h, *w2th, *w3th;
    float *h2f, *cc, *v5;
    cudaGetSymbolAddress((void**)&h1hi, g_h1hi);
    cudaGetSymbolAddress((void**)&h1lo, g_h1lo);
    cudaGetSymbolAddress((void**)&h2f,  g_h2f);
    cudaGetSymbolAddress((void**)&h2h,  g_h2h);
    cudaGetSymbolAddress((void**)&w2th, g_w2th);
    cudaGetSymbolAddress((void**)&w3th, g_w3th);
    cudaGetSymbolAddress((void**)&cc,  g_cc);
    cudaGetSymbolAddress((void**)&v5,  g_v5);

    static bool attr_set = false;
    if (!attr_set) {
        cudaFuncSetAttribute(gemm_h2, cudaFuncAttributeMaxDynamicSharedMemorySize, GEMM2_SMEM);
        cudaFuncSetAttribute(gemm_cc, cudaFuncAttributeMaxDynamicSharedMemorySize, GEMM1_SMEM);
        attr_set = true;
    }

    // 0a) W2^T fp16: [1024][6540] -> [6656-ld rows][1024]
    transpose_h<<<dim3((CS + 31) / 32, (HID + 31) / 32), dim3(32, 8)>>>(
        W2, HID, CS, CS, w2th, HID, 0);
    // 0b) W3^T fp16 + compact: [6540][6528] -> [5440 rows][6656-ld]
    transpose_h<<<dim3((MK + 31) / 32, (CS + 31) / 32), dim3(32, 8)>>>(
        W3, CS, CS, MK, w3th, CSP, 1);

    // 1) h1 = tanh(z @ W1 + b1) -> fp16 hi/lo
    h1_kernel<<<dim3(HID / 128, B_SZ / 128), 256>>>(
        x + (IN_F + 1), XCOLS, W1, HID, b1, h1hi, h1lo);

    // 2) h2 = tanh(h1 @ W2 + b2): 2-pass fp16
    gemm_h2<<<dim3(CSP / 256, B_SZ / 128), 512, GEMM2_SMEM>>>(
        h1hi, h1lo, w2th, b2, h2f, h2h);

    // 3) tail 12 columns -> v5
    tail_v_kernel<<<B_SZ, 128>>>(h2f, W3, b3, x, v5);

    // 4) big GEMM: cc = (h2 @ W3t' + b3) * v5 : 1-pass fp16
    gemm_cc<<<dim3(MK5P / 256, B_SZ / 128), 512, GEMM1_SMEM>>>(
        h2h, w3th, b3, v5, cc);

    // 5) group-of-5 sums + adaptive linear
    final_kernel<<<B_SZ, 256>>>(cc, x, out);
}

// round 8
// speedup vs baseline: 2.0325x; 1.0329x over previous
#include <cuda_runtime.h>
#include <cuda_fp16.h>
#include <math.h>
#include <stdint.h>

// ---------------- problem constants ----------------
#define B_SZ   8192
#define XCOLS  145
#define IN_F   16
#define LAT    128
#define HID    1024
#define CS     6540     // (M+2)*K
#define CSP    6656     // CS padded to 256
#define MK     6528     // M*K
#define MK5    5440     // compacted (drop k%6==3, v==0)
#define MK5P   5632     // padded to 256

// ---------------- scratch (zero-initialized device globals) -----------------
__device__ __half g_h1hi[(size_t)B_SZ * HID];
__device__ __half g_h1lo[(size_t)B_SZ * HID];
__device__ __half g_h2h [(size_t)B_SZ * CSP];     // pads stay zero
__device__ __half g_w2th[(size_t)CSP * HID];      // W2^T, pad rows zero
__device__ __half g_w3th[(size_t)MK5P * CSP];     // W3^T compact, pads zero
__device__ float  g_w3t12[(size_t)12 * CSP];      // tail cols [12][CSP], pads zero
__device__ float  g_cc  [(size_t)B_SZ * MK5];
__device__ float  g_v5  [(size_t)B_SZ * 5];

// ---------------- low-level helpers ----------------
__device__ __forceinline__ uint32_t smem_u32(const void* p) {
    uint32_t a;
    asm("{ .reg .u64 t; cvta.to.shared.u64 t, %1; cvt.u32.u64 %0, t; }" : "=r"(a) : "l"(p));
    return a;
}
__device__ __forceinline__ void cpa16(uint32_t dst, const void* src) {
    asm volatile("cp.async.cg.shared.global [%0], [%1], 16;" :: "r"(dst), "l"(src));
}
#define CP_COMMIT() asm volatile("cp.async.commit_group;" ::: "memory")
#define CP_WAIT2()  asm volatile("cp.async.wait_group 2;" ::: "memory")

__device__ __forceinline__ void ldsm4(uint32_t& r0, uint32_t& r1, uint32_t& r2, uint32_t& r3,
                                      uint32_t addr) {
    asm volatile("ldmatrix.sync.aligned.m8n8.x4.shared.b16 {%0,%1,%2,%3}, [%4];"
                 : "=r"(r0), "=r"(r1), "=r"(r2), "=r"(r3) : "r"(addr));
}
__device__ __forceinline__ void mma_f16(float* c, const uint32_t* a, uint32_t b0, uint32_t b1) {
    asm volatile(
        "mma.sync.aligned.m16n8k16.row.col.f32.f16.f16.f32 "
        "{%0,%1,%2,%3}, {%4,%5,%6,%7}, {%8,%9}, {%0,%1,%2,%3};"
        : "+f"(c[0]), "+f"(c[1]), "+f"(c[2]), "+f"(c[3])
        : "r"(a[0]), "r"(a[1]), "r"(a[2]), "r"(a[3]), "r"(b0), "r"(b1));
}

// ============================================================================
// GEMM A: 2-pass fp16, tile 128x128, BK=32, 3 stages, 256 thr, 2 CTAs/SM.
// warp tile: 32m x 64n  (warp_m in 0..3, warp_n in 0..1)
// h2 = tanh(h1 @ W2t^T + b2) -> h2h (fp16)
// ============================================================================
#define ROWB2    80
#define A2LO     10240
#define B2OFF    20480
#define STG2     30720
#define GEMM2_SMEM (3 * STG2)   // 92160

__global__ __launch_bounds__(256, 2)
void gemm_h2(const __half* __restrict__ Ahi, const __half* __restrict__ Alo,
             const __half* __restrict__ Bh,
             const float* __restrict__ bias,
             __half* __restrict__ outh)
{
    extern __shared__ char smem[];
    const uint32_t sbase = smem_u32(smem);
    const int tid  = threadIdx.x;
    const int lane = tid & 31;
    const int wid  = tid >> 5;
    const int warp_m = wid & 3;
    const int warp_n = wid >> 2;          // 0..1
    const int bm = blockIdx.y * 128;
    const int bn = blockIdx.x * 128;

    const int lrow = tid >> 1;            // 0..127
    const int lhalf = tid & 1;            // 0..1
    const char* aHiSrc = (const char*)(Ahi + (size_t)(bm + lrow) * HID) + lhalf * 32;
    const char* aLoSrc = (const char*)(Alo + (size_t)(bm + lrow) * HID) + lhalf * 32;
    const char* bSrc   = (const char*)(Bh  + (size_t)(bn + lrow) * HID) + lhalf * 32;
    const uint32_t dA = lrow * ROWB2 + lhalf * 32;

    float acc[2][8][4];
    #pragma unroll
    for (int i = 0; i < 2; ++i)
        #pragma unroll
        for (int j = 0; j < 8; ++j)
            #pragma unroll
            for (int l = 0; l < 4; ++l) acc[i][j][l] = 0.f;

    auto load_stage = [&](int s, int kc) {
        const uint32_t sA = sbase + s * STG2;
        const size_t kb = (size_t)kc * 64;
        cpa16(sA + dA,       aHiSrc + kb);
        cpa16(sA + dA + 16,  aHiSrc + kb + 16);
        cpa16(sA + A2LO + dA,      aLoSrc + kb);
        cpa16(sA + A2LO + dA + 16, aLoSrc + kb + 16);
        cpa16(sA + B2OFF + dA,      bSrc + kb);
        cpa16(sA + B2OFF + dA + 16, bSrc + kb + 16);
    };

    const int nk = HID / 32;   // 32
    load_stage(0, 0); CP_COMMIT();
    load_stage(1, 1); CP_COMMIT();

    const int l15  = lane & 15;
    const int lksl = (lane >> 4) & 1;

    for (int k = 0; k < nk; ++k) {
        const int fetch = k + 2;
        if (fetch < nk) load_stage(fetch % 3, fetch);
        CP_COMMIT();
        CP_WAIT2();
        __syncthreads();

        const uint32_t sA = sbase + (k % 3) * STG2;
        const uint32_t sB = sA + B2OFF;

        #pragma unroll
        for (int ks = 0; ks < 2; ++ks) {
            const uint32_t koff = ks * 32 + lksl * 16;
            uint32_t ahi[2][4], alo[2][4];
            #pragma unroll
            for (int mt = 0; mt < 2; ++mt) {
                uint32_t ra = sA + (uint32_t)(warp_m * 32 + mt * 16 + l15) * ROWB2 + koff;
                ldsm4(ahi[mt][0], ahi[mt][1], ahi[mt][2], ahi[mt][3], ra);
                ldsm4(alo[mt][0], alo[mt][1], alo[mt][2], alo[mt][3], ra + A2LO);
            }
            uint32_t bh[2][4];
            {
                uint32_t rb = sB + (uint32_t)(warp_n * 64 + l15) * ROWB2 + koff;
                ldsm4(bh[0][0], bh[0][1], bh[0][2], bh[0][3], rb);
            }
            #pragma unroll
            for (int g = 0; g < 4; ++g) {
                const int cur = g & 1, nxt = cur ^ 1;
                if (g < 3) {
                    uint32_t rb = sB + (uint32_t)(warp_n * 64 + (g + 1) * 16 + l15) * ROWB2 + koff;
                    ldsm4(bh[nxt][0], bh[nxt][1], bh[nxt][2], bh[nxt][3], rb);
                }
                float* c00 = acc[0][2 * g];
                float* c01 = acc[0][2 * g + 1];
                float* c10 = acc[1][2 * g];
                float* c11 = acc[1][2 * g + 1];
                mma_f16(c00, ahi[0], bh[cur][0], bh[cur][2]);
                mma_f16(c01, ahi[0], bh[cur][1], bh[cur][3]);
                mma_f16(c10, ahi[1], bh[cur][0], bh[cur][2]);
                mma_f16(c11, ahi[1], bh[cur][1], bh[cur][3]);
                mma_f16(c00, alo[0], bh[cur][0], bh[cur][2]);
                mma_f16(c01, alo[0], bh[cur][1], bh[cur][3]);
                mma_f16(c10, alo[1], bh[cur][0], bh[cur][2]);
                mma_f16(c11, alo[1], bh[cur][1], bh[cur][3]);
            }
        }
        __syncthreads();
    }

    // epilogue: tanh(+bias) -> fp16 (pads [CS,CSP) untouched -> stay zero)
    #pragma unroll
    for (int mt = 0; mt < 2; ++mt) {
        #pragma unroll
        for (int h = 0; h < 2; ++h) {
            const int row = bm + warp_m * 32 + mt * 16 + (lane >> 2) + h * 8;
            #pragma unroll
            for (int nt = 0; nt < 8; ++nt) {
                const int col = bn + warp_n * 64 + nt * 8 + ((lane & 3) << 1);
                if (col < CS) {
                    float t0 = tanhf(acc[mt][nt][h * 2 + 0] + bias[col]);
                    float t1 = tanhf(acc[mt][nt][h * 2 + 1] + bias[col + 1]);
                    __half2 hp;
                    hp.x = __float2half(t0);
                    hp.y = __float2half(t1);
                    *reinterpret_cast<__half2*>(outh + (size_t)row * CSP + col) = hp;
                }
            }
        }
    }
}

// ============================================================================
// GEMM B: 1-pass fp16, tile 128x128, BK=64, 3 stages, 256 thr, 2 CTAs/SM.
// warp tile: 32m x 64n
// cc = (h2h @ W3t^T + b3[expand]) * v5
// ============================================================================
#define ROWB1    144
#define B1OFF    (128 * ROWB1)          // 18432
#define STG1     (256 * ROWB1)          // 36864
#define GEMM1_SMEM (3 * STG1)           // 110592

__global__ __launch_bounds__(256, 2)
void gemm_cc(const __half* __restrict__ A, const __half* __restrict__ B,
             const float* __restrict__ bias, const float* __restrict__ v5,
             float* __restrict__ outf)
{
    extern __shared__ char smem[];
    const uint32_t sbase = smem_u32(smem);
    const int tid  = threadIdx.x;
    const int lane = tid & 31;
    const int wid  = tid >> 5;
    const int warp_m = wid & 3;
    const int warp_n = wid >> 2;          // 0..1
    const int bm = blockIdx.y * 128;
    const int bn = blockIdx.x * 128;

    const int lrow = tid >> 1;
    const int lhalf = tid & 1;
    const char* aSrc = (const char*)(A + (size_t)(bm + lrow) * CSP) + lhalf * 64;
    const char* bSrc = (const char*)(B + (size_t)(bn + lrow) * CSP) + lhalf * 64;
    const uint32_t dA = lrow * ROWB1 + lhalf * 64;

    float acc[2][8][4];
    #pragma unroll
    for (int i = 0; i < 2; ++i)
        #pragma unroll
        for (int j = 0; j < 8; ++j)
            #pragma unroll
            for (int l = 0; l < 4; ++l) acc[i][j][l] = 0.f;

    auto load_stage = [&](int s, int kc) {
        const uint32_t sA = sbase + s * STG1;
        const size_t kb = (size_t)kc * 128;
        #pragma unroll
        for (int j = 0; j < 4; ++j) {
            cpa16(sA + dA + j * 16,         aSrc + kb + j * 16);
            cpa16(sA + B1OFF + dA + j * 16, bSrc + kb + j * 16);
        }
    };

    const int nk = CSP / 64;   // 104 (pads zero)
    load_stage(0, 0); CP_COMMIT();
    load_stage(1, 1); CP_COMMIT();

    const int l15  = lane & 15;
    const int lksl = (lane >> 4) & 1;

    for (int k = 0; k < nk; ++k) {
        const int fetch = k + 2;
        if (fetch < nk) load_stage(fetch % 3, fetch);
        CP_COMMIT();
        CP_WAIT2();
        __syncthreads();

        const uint32_t sA = sbase + (k % 3) * STG1;
        const uint32_t sB = sA + B1OFF;

        #pragma unroll
        for (int ks = 0; ks < 4; ++ks) {
            const uint32_t koff = ks * 32 + lksl * 16;
            uint32_t a[2][4];
            #pragma unroll
            for (int mt = 0; mt < 2; ++mt) {
                uint32_t ra = sA + (uint32_t)(warp_m * 32 + mt * 16 + l15) * ROWB1 + koff;
                ldsm4(a[mt][0], a[mt][1], a[mt][2], a[mt][3], ra);
            }
            uint32_t bh[2][4];
            {
                uint32_t rb = sB + (uint32_t)(warp_n * 64 + l15) * ROWB1 + koff;
                ldsm4(bh[0][0], bh[0][1], bh[0][2], bh[0][3], rb);
            }
            #pragma unroll
            for (int g = 0; g < 4; ++g) {
                const int cur = g & 1, nxt = cur ^ 1;
                if (g < 3) {
                    uint32_t rb = sB + (uint32_t)(warp_n * 64 + (g + 1) * 16 + l15) * ROWB1 + koff;
                    ldsm4(bh[nxt][0], bh[nxt][1], bh[nxt][2], bh[nxt][3], rb);
                }
                mma_f16(acc[0][2 * g],     a[0], bh[cur][0], bh[cur][2]);
                mma_f16(acc[0][2 * g + 1], a[0], bh[cur][1], bh[cur][3]);
                mma_f16(acc[1][2 * g],     a[1], bh[cur][0], bh[cur][2]);
                mma_f16(acc[1][2 * g + 1], a[1], bh[cur][1], bh[cur][3]);
            }
        }
        __syncthreads();
    }

    // epilogue: (+bias[expanded]) * v5
    #pragma unroll
    for (int mt = 0; mt < 2; ++mt) {
        #pragma unroll
        for (int h = 0; h < 2; ++h) {
            const int row = bm + warp_m * 32 + mt * 16 + (lane >> 2) + h * 8;
            #pragma unroll
            for (int nt = 0; nt < 8; ++nt) {
                const int col = bn + warp_n * 64 + nt * 8 + ((lane & 3) << 1);
                #pragma unroll
                for (int e = 0; e < 2; ++e) {
                    int c = col + e;
                    if (c < MK5) {
                        float val = acc[mt][nt][h * 2 + e];
                        int m6 = c / 5, j5 = c - m6 * 5;
                        int kk = (j5 < 3) ? j5 : j5 + 1;
                        float sc = v5[(size_t)row * 5 + j5];
                        outf[(size_t)row * MK5 + c] = (val + bias[m6 * 6 + kk]) * sc;
                    }
                }
            }
        }
    }
}

// ---------------- transpose + fp16 (optionally compact k%6==3) --------------
__global__ __launch_bounds__(256)
void transpose_h(const float* __restrict__ W, int R, int Cstride, int nlimit,
                 __half* __restrict__ Thi, int ldt, int compact)
{
    __shared__ float ts[32][33];
    const int tx = threadIdx.x, ty = threadIdx.y;
    const int n0 = blockIdx.x * 32, k0 = blockIdx.y * 32;
    #pragma unroll
    for (int i = 0; i < 32; i += 8) {
        int k = k0 + ty + i, n = n0 + tx;
        ts[ty + i][tx] = (k < R && n < nlimit) ? W[(size_t)k * Cstride + n] : 0.f;
    }
    __syncthreads();
    #pragma unroll
    for (int i = 0; i < 32; i += 8) {
        int n = n0 + ty + i, k = k0 + tx;
        if (n < nlimit && k < R) {
            int np = n;
            if (compact) {
                int r6 = n % 6;
                if (r6 == 3) continue;
                np = (n / 6) * 5 + (r6 < 3 ? r6 : r6 - 1);
            }
            Thi[(size_t)np * ldt + k] = __float2half(ts[tx][ty + i]);
        }
    }
}

// ---------------- gather W3 tail cols -> [12][CSP] --------------------------
__global__ __launch_bounds__(256)
void gather_tail(const float* __restrict__ W3, float* __restrict__ w3t12)
{
    int i = blockIdx.x * 256 + threadIdx.x;
    if (i < CS * 12) {
        int c = i / 12, j = i % 12;
        w3t12[(size_t)j * CSP + c] = W3[(size_t)c * CS + MK + j];
    }
}

// ---------------- h1 = tanh(z @ W1 + b1), SIMT -> fp16 hi/lo ----------------
__global__ __launch_bounds__(256, 2)
void h1_kernel(const float* __restrict__ A, int lda,
               const float* __restrict__ Bm, int ldb,
               const float* __restrict__ bias,
               __half* __restrict__ outHi, __half* __restrict__ outLo)
{
    __shared__ float As[16][128 + 4];
    __shared__ float Bs[16][128 + 4];
    const int tid = threadIdx.x;
    const int bm = blockIdx.y * 128, bn = blockIdx.x * 128;
    const int tx = tid % 16, ty = tid / 16;
    float acc[8][8];
    #pragma unroll
    for (int i = 0; i < 8; ++i)
        #pragma unroll
        for (int j = 0; j < 8; ++j) acc[i][j] = 0.f;

    for (int k0 = 0; k0 < LAT; k0 += 16) {
        #pragma unroll
        for (int i = 0; i < 8; ++i) {
            int idx = tid + i * 256;
            int m = idx / 16, k = idx % 16;
            As[k][m] = A[(size_t)(bm + m) * lda + k0 + k];
        }
        #pragma unroll
        for (int i = 0; i < 8; ++i) {
            int idx = tid + i * 256;
            int k = idx / 128, n = idx % 128;
            Bs[k][n] = Bm[(size_t)(k0 + k) * ldb + bn + n];
        }
        __syncthreads();
        #pragma unroll
        for (int k = 0; k < 16; ++k) {
            float ra[8], rb[8];
            #pragma unroll
            for (int i = 0; i < 8; ++i) ra[i] = As[k][ty * 8 + i];
            #pragma unroll
            for (int j = 0; j < 8; ++j) rb[j] = Bs[k][tx * 8 + j];
            #pragma unroll
            for (int i = 0; i < 8; ++i)
                #pragma unroll
                for (int j = 0; j < 8; ++j) acc[i][j] = fmaf(ra[i], rb[j], acc[i][j]);
        }
        __syncthreads();
    }
    #pragma unroll
    for (int i = 0; i < 8; ++i) {
        int row = bm + ty * 8 + i;
        #pragma unroll
        for (int j = 0; j < 8; ++j) {
            int col = bn + tx * 8 + j;
            float t = tanhf(acc[i][j] + bias[col]);
            __half hi = __float2half(t);
            size_t o = (size_t)row * HID + col;
            outHi[o] = hi;
            outLo[o] = __float2half(t - __half2float(hi));
        }
    }
}

// ---------------- tail GEMM: dtail[b,12] = h2h[b]·w3t12 -> v5 ---------------
__global__ __launch_bounds__(256)
void tail_gemm(const __half* __restrict__ h2h,
               const float* __restrict__ w3t12,
               const float* __restrict__ b3,
               const float* __restrict__ x,
               float* __restrict__ v5)
{
    __shared__ __half h2s[128 * 72];    // 128 rows x 64 k (stride 72)
    __shared__ float  w3s[64 * 12];
    __shared__ float  dt[128 * 12];

    const int tid = threadIdx.x;
    const int bm = blockIdx.x * 128;
    const int bl = tid & 127;
    const int jsel = tid >> 7;          // 0..1

    float acc[6];
    #pragma unroll
    for (int j = 0; j < 6; ++j) acc[j] = 0.f;

    const int lrow = tid >> 1;
    const int lhalf = tid & 1;

    for (int kc = 0; kc < CSP / 64; ++kc) {
        {
            const uint4* src = reinterpret_cast<const uint4*>(
                h2h + (size_t)(bm + lrow) * CSP + kc * 64 + lhalf * 32);
            #pragma unroll
            for (int j = 0; j < 4; ++j) {
                uint4 v = src[j];
                uint32_t off = lrow * 72 + lhalf * 32 + j * 8;
                *reinterpret_cast<uint2*>(&h2s[off])     = make_uint2(v.x, v.y);
                *reinterpret_cast<uint2*>(&h2s[off + 4]) = make_uint2(v.z, v.w);
            }
        }
        for (int i = tid; i < 64 * 12; i += 256) {
            int k = i / 12, j = i % 12;
            w3s[i] = w3t12[(size_t)j * CSP + kc * 64 + k];
        }
        __syncthreads();

        #pragma unroll 8
        for (int k = 0; k < 64; ++k) {
            float hv = __half2float(h2s[bl * 72 + k]);
            #pragma unroll
            for (int j = 0; j < 6; ++j)
                acc[j] = fmaf(hv, w3s[k * 12 + jsel * 6 + j], acc[j]);
        }
        __syncthreads();
    }

    #pragma unroll
    for (int j = 0; j < 6; ++j)
        dt[bl * 12 + jsel * 6 + j] = acc[j] + b3[MK + jsel * 6 + j];
    __syncthreads();

    if (tid < 128) {
        float s = x[(size_t)(B_SZ - 1) * XCOLS + IN_F];
        #pragma unroll
        for (int t5 = 0; t5 < 5; ++t5) {
            int k = (t5 < 3) ? t5 : t5 + 1;
            float sv = fmaf(s, dt[tid * 12 + k], dt[tid * 12 + k + 6]);
            float r = (k < 3) ? cosf(sv * (float)k) : sinf(sv * (float)(k - 3));
            v5[(size_t)(bm + tid) * 5 + t5] = r;
        }
    }
}

// ---------------- final: group-of-5 sums + 16->64 adaptive linear -----------
__global__ __launch_bounds__(256)
void final_kernel(const float* __restrict__ cc,
                  const float* __restrict__ x,
                  float* __restrict__ out)
{
    const int b = blockIdx.x;
    const int t = threadIdx.x;
    __shared__ float row[MK5];
    __shared__ float inp[IN_F];
    const float* src = cc + (size_t)b * MK5;
    for (int i = t; i < MK5; i += 256) row[i] = src[i];
    if (t < IN_F) inp[t] = x[(size_t)b * XCOLS + t];
    __syncthreads();
    if (t < 64) {
        const int o = t;
        float accum = 0.f;
        #pragma unroll
        for (int i = 0; i < IN_F; ++i) {
            const float* g = row + (i * 64 + o) * 5;
            float wsum = ((g[0] + g[1]) + (g[2] + g[3])) + g[4];
            accum = fmaf(inp[i], wsum, accum);
        }
        const float* g = row + (1024 + o) * 5;
        accum += ((g[0] + g[1]) + (g[2] + g[3])) + g[4];
        out[(size_t)b * 64 + o] = accum;
    }
}

// ----------------------------- launch ---------------------------------------
extern "C" void kernel_launch(void* const* d_in, const int* in_sizes, int n_in,
                              void* d_out, int out_size)
{
    const float* x  = (const float*)d_in[0];
    const float* W1 = (const float*)d_in[1];
    const float* b1 = (const float*)d_in[2];
    const float* W2 = (const float*)d_in[3];
    const float* b2 = (const float*)d_in[4];
    const float* W3 = (const float*)d_in[5];
    const float* b3 = (const float*)d_in[6];
    float* out = (float*)d_out;

    __half *h1hi, *h1lo, *h2h, *w2th, *w3th;
    float *w3t12, *cc, *v5;
    cudaGetSymbolAddress((void**)&h1hi, g_h1hi);
    cudaGetSymbolAddress((void**)&h1lo, g_h1lo);
    cudaGetSymbolAddress((void**)&h2h,  g_h2h);
    cudaGetSymbolAddress((void**)&w2th, g_w2th);
    cudaGetSymbolAddress((void**)&w3th, g_w3th);
    cudaGetSymbolAddress((void**)&w3t12, g_w3t12);
    cudaGetSymbolAddress((void**)&cc,  g_cc);
    cudaGetSymbolAddress((void**)&v5,  g_v5);

    static bool attr_set = false;
    if (!attr_set) {
        cudaFuncSetAttribute(gemm_h2, cudaFuncAttributeMaxDynamicSharedMemorySize, GEMM2_SMEM);
        cudaFuncSetAttribute(gemm_cc, cudaFuncAttributeMaxDynamicSharedMemorySize, GEMM1_SMEM);
        attr_set = true;
    }

    // 0a) W2^T fp16
    transpose_h<<<dim3((CS + 31) / 32, (HID + 31) / 32), dim3(32, 8)>>>(
        W2, HID, CS, CS, w2th, HID, 0);
    // 0b) W3^T fp16 + compact
    transpose_h<<<dim3((MK + 31) / 32, (CS + 31) / 32), dim3(32, 8)>>>(
        W3, CS, CS, MK, w3th, CSP, 1);
    // 0c) gather tail columns [12][CSP]
    gather_tail<<<(CS * 12 + 255) / 256, 256>>>(W3, w3t12);

    // 1) h1 = tanh(z @ W1 + b1) -> fp16 hi/lo
    h1_kernel<<<dim3(HID / 128, B_SZ / 128), 256>>>(
        x + (IN_F + 1), XCOLS, W1, HID, b1, h1hi, h1lo);

    // 2) h2 = tanh(h1 @ W2 + b2): 2-pass fp16, 128x128 tiles, 2 CTAs/SM
    gemm_h2<<<dim3(CSP / 128, B_SZ / 128), 256, GEMM2_SMEM>>>(
        h1hi, h1lo, w2th, b2, h2h);

    // 3) tail mini-GEMM -> v5 (reads fp16 h2h; h2f eliminated)
    tail_gemm<<<B_SZ / 128, 256>>>(h2h, w3t12, b3, x, v5);

    // 4) big GEMM: cc = (h2 @ W3t' + b3) * v5, 128x128 tiles, 2 CTAs/SM
    gemm_cc<<<dim3(MK5P / 128, B_SZ / 128), 256, GEMM1_SMEM>>>(
        h2h, w3th, b3, v5, cc);

    // 5) group-of-5 sums + adaptive linear
    final_kernel<<<B_SZ, 256>>>(cc, x, out);
}

// round 9
// speedup vs baseline: 2.1894x; 1.0772x over previous
#include <cuda_runtime.h>
#include <cuda_fp16.h>
#include <math.h>
#include <stdint.h>

// ---------------- problem constants ----------------
#define B_SZ   8192
#define XCOLS  145
#define IN_F   16
#define LAT    128
#define HID    1024
#define CS     6540     // (M+2)*K
#define CSP    6656     // CS padded to 256
#define MK     6528     // M*K
#define MK5    5440     // compacted (drop k%6==3, v==0)
#define MK5P   5632     // padded to 256

// ---------------- scratch (zero-initialized device globals) -----------------
__device__ __half g_zhi [(size_t)B_SZ * LAT];
__device__ __half g_zlo [(size_t)B_SZ * LAT];
__device__ __half g_w1t [(size_t)HID * LAT];      // W1^T [1024][128]
__device__ __half g_h1h [(size_t)B_SZ * HID];
__device__ __half g_h2h [(size_t)B_SZ * CSP];     // pads stay zero
__device__ __half g_w2th[(size_t)CSP * HID];      // W2^T, pad rows zero
__device__ __half g_w3th[(size_t)MK5P * CSP];     // W3^T compact, pads zero
__device__ float  g_w3t12[(size_t)12 * CSP];      // tail cols [12][CSP], pads zero
__device__ float  g_cc  [(size_t)B_SZ * MK5];
__device__ float  g_v5  [(size_t)B_SZ * 5];

// ---------------- low-level helpers ----------------
__device__ __forceinline__ uint32_t smem_u32(const void* p) {
    uint32_t a;
    asm("{ .reg .u64 t; cvta.to.shared.u64 t, %1; cvt.u32.u64 %0, t; }" : "=r"(a) : "l"(p));
    return a;
}
__device__ __forceinline__ void cpa16(uint32_t dst, const void* src) {
    asm volatile("cp.async.cg.shared.global [%0], [%1], 16;" :: "r"(dst), "l"(src));
}
#define CP_COMMIT() asm volatile("cp.async.commit_group;" ::: "memory")
#define CP_WAIT2()  asm volatile("cp.async.wait_group 2;" ::: "memory")

__device__ __forceinline__ void ldsm4(uint32_t& r0, uint32_t& r1, uint32_t& r2, uint32_t& r3,
                                      uint32_t addr) {
    asm volatile("ldmatrix.sync.aligned.m8n8.x4.shared.b16 {%0,%1,%2,%3}, [%4];"
                 : "=r"(r0), "=r"(r1), "=r"(r2), "=r"(r3) : "r"(addr));
}
__device__ __forceinline__ void mma_f16(float* c, const uint32_t* a, uint32_t b0, uint32_t b1) {
    asm volatile(
        "mma.sync.aligned.m16n8k16.row.col.f32.f16.f16.f32 "
        "{%0,%1,%2,%3}, {%4,%5,%6,%7}, {%8,%9}, {%0,%1,%2,%3};"
        : "+f"(c[0]), "+f"(c[1]), "+f"(c[2]), "+f"(c[3])
        : "r"(a[0]), "r"(a[1]), "r"(a[2]), "r"(a[3]), "r"(b0), "r"(b1));
}

// ============================================================================
// Unified fp16 HMMA GEMM: tile 128x128, BK=64, 3 stages, 256 thr.
// warp tile 32m x 64n.  TWOPASS: A = Ahi + Alo (exact A).
// MODE 0: out fp16 = tanh(acc + bias[col])          (ld = ldo)
// MODE 1: out fp32 = (acc + bias[expand(col)]) * v5  (ld = ldo)
// ============================================================================
#define ROWB1 144

template<int MODE, int TWOPASS>
__global__ __launch_bounds__(256, TWOPASS ? 1 : 2)
void gemm_f16(const __half* __restrict__ A, const __half* __restrict__ Alo, int lda,
              const __half* __restrict__ B, int ldb, int nk,
              const float* __restrict__ bias, const float* __restrict__ v5,
              void* __restrict__ outp, int ldo, int Nlimit)
{
    constexpr int ALO_OFF = 128 * ROWB1;
    constexpr int B_OFF   = (TWOPASS ? 256 : 128) * ROWB1;
    constexpr int STG     = (TWOPASS ? 384 : 256) * ROWB1;

    extern __shared__ char smem[];
    const uint32_t sbase = smem_u32(smem);
    const int tid  = threadIdx.x;
    const int lane = tid & 31;
    const int wid  = tid >> 5;
    const int warp_m = wid & 3;
    const int warp_n = wid >> 2;          // 0..1
    const int bm = blockIdx.y * 128;
    const int bn = blockIdx.x * 128;

    const int lrow = tid >> 1;
    const int lhalf = tid & 1;
    const char* aSrc  = (const char*)(A + (size_t)(bm + lrow) * lda) + lhalf * 64;
    const char* alSrc = (const char*)(Alo + (size_t)(bm + lrow) * lda) + lhalf * 64;
    const char* bSrc  = (const char*)(B + (size_t)(bn + lrow) * ldb) + lhalf * 64;
    const uint32_t dA = lrow * ROWB1 + lhalf * 64;

    float acc[2][8][4];
    #pragma unroll
    for (int i = 0; i < 2; ++i)
        #pragma unroll
        for (int j = 0; j < 8; ++j)
            #pragma unroll
            for (int l = 0; l < 4; ++l) acc[i][j][l] = 0.f;

    auto load_stage = [&](int s, int kc) {
        const uint32_t sA = sbase + s * STG;
        const size_t kb = (size_t)kc * 128;   // 64 fp16 = 128B
        #pragma unroll
        for (int j = 0; j < 4; ++j) {
            cpa16(sA + dA + j * 16,         aSrc + kb + j * 16);
            if (TWOPASS) cpa16(sA + ALO_OFF + dA + j * 16, alSrc + kb + j * 16);
            cpa16(sA + B_OFF + dA + j * 16, bSrc + kb + j * 16);
        }
    };

    load_stage(0, 0); CP_COMMIT();
    if (nk > 1) load_stage(1, 1);
    CP_COMMIT();

    const int l15  = lane & 15;
    const int lksl = (lane >> 4) & 1;

    for (int k = 0; k < nk; ++k) {
        const int fetch = k + 2;
        if (fetch < nk) load_stage(fetch % 3, fetch);
        CP_COMMIT();
        CP_WAIT2();
        __syncthreads();

        const uint32_t sA = sbase + (k % 3) * STG;
        const uint32_t sB = sA + B_OFF;

        #pragma unroll
        for (int ks = 0; ks < 4; ++ks) {
            const uint32_t koff = ks * 32 + lksl * 16;
            uint32_t a[2][4], al[2][4];
            #pragma unroll
            for (int mt = 0; mt < 2; ++mt) {
                uint32_t ra = sA + (uint32_t)(warp_m * 32 + mt * 16 + l15) * ROWB1 + koff;
                ldsm4(a[mt][0], a[mt][1], a[mt][2], a[mt][3], ra);
                if (TWOPASS)
                    ldsm4(al[mt][0], al[mt][1], al[mt][2], al[mt][3], ra + ALO_OFF);
            }
            uint32_t bh[2][4];
            {
                uint32_t rb = sB + (uint32_t)(warp_n * 64 + l15) * ROWB1 + koff;
                ldsm4(bh[0][0], bh[0][1], bh[0][2], bh[0][3], rb);
            }
            #pragma unroll
            for (int g = 0; g < 4; ++g) {
                const int cur = g & 1, nxt = cur ^ 1;
                if (g < 3) {
                    uint32_t rb = sB + (uint32_t)(warp_n * 64 + (g + 1) * 16 + l15) * ROWB1 + koff;
                    ldsm4(bh[nxt][0], bh[nxt][1], bh[nxt][2], bh[nxt][3], rb);
                }
                float* c00 = acc[0][2 * g];
                float* c01 = acc[0][2 * g + 1];
                float* c10 = acc[1][2 * g];
                float* c11 = acc[1][2 * g + 1];
                mma_f16(c00, a[0], bh[cur][0], bh[cur][2]);
                mma_f16(c01, a[0], bh[cur][1], bh[cur][3]);
                mma_f16(c10, a[1], bh[cur][0], bh[cur][2]);
                mma_f16(c11, a[1], bh[cur][1], bh[cur][3]);
                if (TWOPASS) {
                    mma_f16(c00, al[0], bh[cur][0], bh[cur][2]);
                    mma_f16(c01, al[0], bh[cur][1], bh[cur][3]);
                    mma_f16(c10, al[1], bh[cur][0], bh[cur][2]);
                    mma_f16(c11, al[1], bh[cur][1], bh[cur][3]);
                }
            }
        }
        __syncthreads();
    }

    // ---------------- epilogue ----------------
    #pragma unroll
    for (int mt = 0; mt < 2; ++mt) {
        #pragma unroll
        for (int h = 0; h < 2; ++h) {
            const int row = bm + warp_m * 32 + mt * 16 + (lane >> 2) + h * 8;
            #pragma unroll
            for (int nt = 0; nt < 8; ++nt) {
                const int col = bn + warp_n * 64 + nt * 8 + ((lane & 3) << 1);
                if (MODE == 0) {
                    if (col < Nlimit) {
                        float t0 = tanhf(acc[mt][nt][h * 2 + 0] + bias[col]);
                        float t1 = tanhf(acc[mt][nt][h * 2 + 1] + bias[col + 1]);
                        __half2 hp;
                        hp.x = __float2half(t0);
                        hp.y = __float2half(t1);
                        *reinterpret_cast<__half2*>((__half*)outp + (size_t)row * ldo + col) = hp;
                    }
                } else {
                    #pragma unroll
                    for (int e = 0; e < 2; ++e) {
                        int c = col + e;
                        if (c < Nlimit) {
                            float val = acc[mt][nt][h * 2 + e];
                            int m6 = c / 5, j5 = c - m6 * 5;
                            int kk = (j5 < 3) ? j5 : j5 + 1;
                            float sc = v5[(size_t)row * 5 + j5];
                            ((float*)outp)[(size_t)row * ldo + c] = (val + bias[m6 * 6 + kk]) * sc;
                        }
                    }
                }
            }
        }
    }
}

// ---------------- transpose + fp16 (optionally compact k%6==3) --------------
__global__ __launch_bounds__(256)
void transpose_h(const float* __restrict__ W, int R, int Cstride, int nlimit,
                 __half* __restrict__ Thi, int ldt, int compact)
{
    __shared__ float ts[32][33];
    const int tx = threadIdx.x, ty = threadIdx.y;
    const int n0 = blockIdx.x * 32, k0 = blockIdx.y * 32;
    #pragma unroll
    for (int i = 0; i < 32; i += 8) {
        int k = k0 + ty + i, n = n0 + tx;
        ts[ty + i][tx] = (k < R && n < nlimit) ? W[(size_t)k * Cstride + n] : 0.f;
    }
    __syncthreads();
    #pragma unroll
    for (int i = 0; i < 32; i += 8) {
        int n = n0 + ty + i, k = k0 + tx;
        if (n < nlimit && k < R) {
            int np = n;
            if (compact) {
                int r6 = n % 6;
                if (r6 == 3) continue;
                np = (n / 6) * 5 + (r6 < 3 ? r6 : r6 - 1);
            }
            Thi[(size_t)np * ldt + k] = __float2half(ts[tx][ty + i]);
        }
    }
}

// ---------------- gather W3 tail cols -> [12][CSP] --------------------------
__global__ __launch_bounds__(256)
void gather_tail(const float* __restrict__ W3, float* __restrict__ w3t12)
{
    int i = blockIdx.x * 256 + threadIdx.x;
    if (i < CS * 12) {
        int c = i / 12, j = i % 12;
        w3t12[(size_t)j * CSP + c] = W3[(size_t)c * CS + MK + j];
    }
}

// ---------------- z -> fp16 hi/lo (contiguous [B][128]) ---------------------
__global__ __launch_bounds__(256)
void zprep(const float* __restrict__ x, __half* __restrict__ zhi, __half* __restrict__ zlo)
{
    int i = blockIdx.x * 256 + threadIdx.x;
    if (i < B_SZ * LAT) {
        int b = i >> 7, c = i & 127;
        float v = x[(size_t)b * XCOLS + (IN_F + 1) + c];
        __half h = __float2half(v);
        zhi[i] = h;
        zlo[i] = __float2half(v - __half2float(h));
    }
}

// ---------------- tail GEMM: dtail[b,12] = h2h[b]·w3t12 -> v5 ---------------
__global__ __launch_bounds__(256)
void tail_gemm(const __half* __restrict__ h2h,
               const float* __restrict__ w3t12,
               const float* __restrict__ b3,
               const float* __restrict__ x,
               float* __restrict__ v5)
{
    __shared__ __half h2s[128 * 72];
    __shared__ float  w3s[64 * 12];
    __shared__ float  dt[128 * 12];

    const int tid = threadIdx.x;
    const int bm = blockIdx.x * 128;
    const int bl = tid & 127;
    const int jsel = tid >> 7;

    float acc[6];
    #pragma unroll
    for (int j = 0; j < 6; ++j) acc[j] = 0.f;

    const int lrow = tid >> 1;
    const int lhalf = tid & 1;

    for (int kc = 0; kc < CSP / 64; ++kc) {
        {
            const uint4* src = reinterpret_cast<const uint4*>(
                h2h + (size_t)(bm + lrow) * CSP + kc * 64 + lhalf * 32);
            #pragma unroll
            for (int j = 0; j < 4; ++j) {
                uint4 v = src[j];
                uint32_t off = lrow * 72 + lhalf * 32 + j * 8;
                *reinterpret_cast<uint2*>(&h2s[off])     = make_uint2(v.x, v.y);
                *reinterpret_cast<uint2*>(&h2s[off + 4]) = make_uint2(v.z, v.w);
            }
        }
        for (int i = tid; i < 64 * 12; i += 256) {
            int k = i / 12, j = i % 12;
            w3s[i] = w3t12[(size_t)j * CSP + kc * 64 + k];
        }
        __syncthreads();

        #pragma unroll 8
        for (int k = 0; k < 64; ++k) {
            float hv = __half2float(h2s[bl * 72 + k]);
            #pragma unroll
            for (int j = 0; j < 6; ++j)
                acc[j] = fmaf(hv, w3s[k * 12 + jsel * 6 + j], acc[j]);
        }
        __syncthreads();
    }

    #pragma unroll
    for (int j = 0; j < 6; ++j)
        dt[bl * 12 + jsel * 6 + j] = acc[j] + b3[MK + jsel * 6 + j];
    __syncthreads();

    if (tid < 128) {
        float s = x[(size_t)(B_SZ - 1) * XCOLS + IN_F];
        #pragma unroll
        for (int t5 = 0; t5 < 5; ++t5) {
            int k = (t5 < 3) ? t5 : t5 + 1;
            float sv = fmaf(s, dt[tid * 12 + k], dt[tid * 12 + k + 6]);
            float r = (k < 3) ? cosf(sv * (float)k) : sinf(sv * (float)(k - 3));
            v5[(size_t)(bm + tid) * 5 + t5] = r;
        }
    }
}

// ---------------- final: group-of-5 sums + 16->64 adaptive linear -----------
__global__ __launch_bounds__(256)
void final_kernel(const float* __restrict__ cc,
                  const float* __restrict__ x,
                  float* __restrict__ out)
{
    const int b = blockIdx.x;
    const int t = threadIdx.x;
    __shared__ float row[MK5];
    __shared__ float inp[IN_F];
    const float* src = cc + (size_t)b * MK5;
    for (int i = t; i < MK5; i += 256) row[i] = src[i];
    if (t < IN_F) inp[t] = x[(size_t)b * XCOLS + t];
    __syncthreads();
    if (t < 64) {
        const int o = t;
        float accum = 0.f;
        #pragma unroll
        for (int i = 0; i < IN_F; ++i) {
            const float* g = row + (i * 64 + o) * 5;
            float wsum = ((g[0] + g[1]) + (g[2] + g[3])) + g[4];
            accum = fmaf(inp[i], wsum, accum);
        }
        const float* g = row + (1024 + o) * 5;
        accum += ((g[0] + g[1]) + (g[2] + g[3])) + g[4];
        out[(size_t)b * 64 + o] = accum;
    }
}

// ----------------------------- launch ---------------------------------------
extern "C" void kernel_launch(void* const* d_in, const int* in_sizes, int n_in,
                              void* d_out, int out_size)
{
    const float* x  = (const float*)d_in[0];
    const float* W1 = (const float*)d_in[1];
    const float* b1 = (const float*)d_in[2];
    const float* W2 = (const float*)d_in[3];
    const float* b2 = (const float*)d_in[4];
    const float* W3 = (const float*)d_in[5];
    const float* b3 = (const float*)d_in[6];
    float* out = (float*)d_out;

    __half *zhi, *zlo, *w1t, *h1h, *h2h, *w2th, *w3th;
    float *w3t12, *cc, *v5;
    cudaGetSymbolAddress((void**)&zhi,  g_zhi);
    cudaGetSymbolAddress((void**)&zlo,  g_zlo);
    cudaGetSymbolAddress((void**)&w1t,  g_w1t);
    cudaGetSymbolAddress((void**)&h1h,  g_h1h);
    cudaGetSymbolAddress((void**)&h2h,  g_h2h);
    cudaGetSymbolAddress((void**)&w2th, g_w2th);
    cudaGetSymbolAddress((void**)&w3th, g_w3th);
    cudaGetSymbolAddress((void**)&w3t12, g_w3t12);
    cudaGetSymbolAddress((void**)&cc,  g_cc);
    cudaGetSymbolAddress((void**)&v5,  g_v5);

    const int SM_2P = 3 * 384 * ROWB1;   // 165888
    const int SM_1P = 3 * 256 * ROWB1;   // 110592

    static bool attr_set = false;
    if (!attr_set) {
        cudaFuncSetAttribute(gemm_f16<0, 1>, cudaFuncAttributeMaxDynamicSharedMemorySize, SM_2P);
        cudaFuncSetAttribute(gemm_f16<0, 0>, cudaFuncAttributeMaxDynamicSharedMemorySize, SM_1P);
        cudaFuncSetAttribute(gemm_f16<1, 0>, cudaFuncAttributeMaxDynamicSharedMemorySize, SM_1P);
        attr_set = true;
    }

    // 0) weight prep
    transpose_h<<<dim3((CS + 31) / 32, (HID + 31) / 32), dim3(32, 8)>>>(
        W2, HID, CS, CS, w2th, HID, 0);
    transpose_h<<<dim3((MK + 31) / 32, (CS + 31) / 32), dim3(32, 8)>>>(
        W3, CS, CS, MK, w3th, CSP, 1);
    transpose_h<<<dim3((HID + 31) / 32, (LAT + 31) / 32), dim3(32, 8)>>>(
        W1, LAT, HID, HID, w1t, LAT, 0);
    gather_tail<<<(CS * 12 + 255) / 256, 256>>>(W3, w3t12);
    zprep<<<(B_SZ * LAT + 255) / 256, 256>>>(x, zhi, zlo);

    // 1) h1 = tanh(z @ W1 + b1): 2-pass (exact z), K=128
    gemm_f16<0, 1><<<dim3(HID / 128, B_SZ / 128), 256, SM_2P>>>(
        zhi, zlo, LAT, w1t, LAT, LAT / 64, b1, nullptr, h1h, HID, HID);

    // 2) h2 = tanh(h1 @ W2 + b2): 1-pass, K=1024
    gemm_f16<0, 0><<<dim3(CSP / 128, B_SZ / 128), 256, SM_1P>>>(
        h1h, nullptr, HID, w2th, HID, HID / 64, b2, nullptr, h2h, CSP, CS);

    // 3) tail mini-GEMM -> v5
    tail_gemm<<<B_SZ / 128, 256>>>(h2h, w3t12, b3, x, v5);

    // 4) big GEMM: cc = (h2 @ W3t' + b3) * v5, 1-pass, K=CSP
    gemm_f16<1, 0><<<dim3(MK5P / 128, B_SZ / 128), 256, SM_1P>>>(
        h2h, nullptr, CSP, w3th, CSP, CSP / 64, b3, v5, cc, MK5, MK5);

    // 5) group-of-5 sums + adaptive linear
    final_kernel<<<B_SZ, 256>>>(cc, x, out);
}

// round 10
// speedup vs baseline: 2.9449x; 1.3450x over previous
#include <cuda_runtime.h>
#include <cuda_fp16.h>
#include <math.h>
#include <stdint.h>

// ---------------- problem constants ----------------
#define B_SZ   8192
#define XCOLS  145
#define IN_F   16
#define LAT    128
#define HID    1024
#define CS     6540     // (M+2)*K
#define CSP    6656     // CS padded to 256
#define MK     6528     // M*K
#define MK5    5440     // compacted (drop k%6==3, v==0); = 34*160
#define NGRP   1088     // MK5/5

// ---------------- scratch (zero-initialized device globals) -----------------
__device__ __half g_zhi [(size_t)B_SZ * LAT];
__device__ __half g_zlo [(size_t)B_SZ * LAT];
__device__ __half g_w1t [(size_t)HID * LAT];
__device__ __half g_h1h [(size_t)B_SZ * HID];
__device__ __half g_h2h [(size_t)B_SZ * CSP];     // pads stay zero
__device__ __half g_w2th[(size_t)CSP * HID];
__device__ __half g_w3th[(size_t)MK5 * CSP];      // compact, K-pads zero
__device__ float  g_w3t12[(size_t)12 * CSP];      // tail cols, pads zero
__device__ float  g_bias5[(size_t)MK5];           // expanded b3 per compact col
__device__ float  g_w   [(size_t)B_SZ * NGRP];    // fused weights
__device__ float  g_v5  [(size_t)B_SZ * 5];

// ---------------- low-level helpers ----------------
__device__ __forceinline__ uint32_t smem_u32(const void* p) {
    uint32_t a;
    asm("{ .reg .u64 t; cvta.to.shared.u64 t, %1; cvt.u32.u64 %0, t; }" : "=r"(a) : "l"(p));
    return a;
}
__device__ __forceinline__ void cpa16(uint32_t dst, const void* src) {
    asm volatile("cp.async.cg.shared.global [%0], [%1], 16;" :: "r"(dst), "l"(src));
}
#define CP_COMMIT() asm volatile("cp.async.commit_group;" ::: "memory")
#define CP_WAIT2()  asm volatile("cp.async.wait_group 2;" ::: "memory")
#define CP_WAIT0()  asm volatile("cp.async.wait_group 0;" ::: "memory")

__device__ __forceinline__ void ldsm4(uint32_t& r0, uint32_t& r1, uint32_t& r2, uint32_t& r3,
                                      uint32_t addr) {
    asm volatile("ldmatrix.sync.aligned.m8n8.x4.shared.b16 {%0,%1,%2,%3}, [%4];"
                 : "=r"(r0), "=r"(r1), "=r"(r2), "=r"(r3) : "r"(addr));
}
__device__ __forceinline__ void mma_f16(float* c, const uint32_t* a, uint32_t b0, uint32_t b1) {
    asm volatile(
        "mma.sync.aligned.m16n8k16.row.col.f32.f16.f16.f32 "
        "{%0,%1,%2,%3}, {%4,%5,%6,%7}, {%8,%9}, {%0,%1,%2,%3};"
        : "+f"(c[0]), "+f"(c[1]), "+f"(c[2]), "+f"(c[3])
        : "r"(a[0]), "r"(a[1]), "r"(a[2]), "r"(a[3]), "r"(b0), "r"(b1));
}

// ============================================================================
// GEMM (h1 / h2): fp16 HMMA, tile 128x128, BK=64, 3 stages, 256 thr.
// TWOPASS: A = Ahi + Alo.  out fp16 = tanh(acc + bias[col])
// ============================================================================
#define ROWB1 144

template<int TWOPASS>
__global__ __launch_bounds__(256, TWOPASS ? 1 : 2)
void gemm_f16(const __half* __restrict__ A, const __half* __restrict__ Alo, int lda,
              const __half* __restrict__ B, int ldb, int nk,
              const float* __restrict__ bias,
              __half* __restrict__ outp, int ldo, int Nlimit)
{
    constexpr int ALO_OFF = 128 * ROWB1;
    constexpr int B_OFF   = (TWOPASS ? 256 : 128) * ROWB1;
    constexpr int STG     = (TWOPASS ? 384 : 256) * ROWB1;

    extern __shared__ char smem[];
    const uint32_t sbase = smem_u32(smem);
    const int tid  = threadIdx.x;
    const int lane = tid & 31;
    const int wid  = tid >> 5;
    const int warp_m = wid & 3;
    const int warp_n = wid >> 2;
    const int bm = blockIdx.y * 128;
    const int bn = blockIdx.x * 128;

    const int lrow = tid >> 1;
    const int lhalf = tid & 1;
    const char* aSrc  = (const char*)(A + (size_t)(bm + lrow) * lda) + lhalf * 64;
    const char* alSrc = (const char*)(Alo + (size_t)(bm + lrow) * lda) + lhalf * 64;
    const char* bSrc  = (const char*)(B + (size_t)(bn + lrow) * ldb) + lhalf * 64;
    const uint32_t dA = lrow * ROWB1 + lhalf * 64;

    float acc[2][8][4];
    #pragma unroll
    for (int i = 0; i < 2; ++i)
        #pragma unroll
        for (int j = 0; j < 8; ++j)
            #pragma unroll
            for (int l = 0; l < 4; ++l) acc[i][j][l] = 0.f;

    auto load_stage = [&](int s, int kc) {
        const uint32_t sA = sbase + s * STG;
        const size_t kb = (size_t)kc * 128;
        #pragma unroll
        for (int j = 0; j < 4; ++j) {
            cpa16(sA + dA + j * 16,         aSrc + kb + j * 16);
            if (TWOPASS) cpa16(sA + ALO_OFF + dA + j * 16, alSrc + kb + j * 16);
            cpa16(sA + B_OFF + dA + j * 16, bSrc + kb + j * 16);
        }
    };

    load_stage(0, 0); CP_COMMIT();
    if (nk > 1) load_stage(1, 1);
    CP_COMMIT();

    const int l15  = lane & 15;
    const int lksl = (lane >> 4) & 1;

    for (int k = 0; k < nk; ++k) {
        const int fetch = k + 2;
        if (fetch < nk) load_stage(fetch % 3, fetch);
        CP_COMMIT();
        CP_WAIT2();
        __syncthreads();

        const uint32_t sA = sbase + (k % 3) * STG;
        const uint32_t sB = sA + B_OFF;

        #pragma unroll
        for (int ks = 0; ks < 4; ++ks) {
            const uint32_t koff = ks * 32 + lksl * 16;
            uint32_t a[2][4], al[2][4];
            #pragma unroll
            for (int mt = 0; mt < 2; ++mt) {
                uint32_t ra = sA + (uint32_t)(warp_m * 32 + mt * 16 + l15) * ROWB1 + koff;
                ldsm4(a[mt][0], a[mt][1], a[mt][2], a[mt][3], ra);
                if (TWOPASS)
                    ldsm4(al[mt][0], al[mt][1], al[mt][2], al[mt][3], ra + ALO_OFF);
            }
            uint32_t bh[2][4];
            {
                uint32_t rb = sB + (uint32_t)(warp_n * 64 + l15) * ROWB1 + koff;
                ldsm4(bh[0][0], bh[0][1], bh[0][2], bh[0][3], rb);
            }
            #pragma unroll
            for (int g = 0; g < 4; ++g) {
                const int cur = g & 1, nxt = cur ^ 1;
                if (g < 3) {
                    uint32_t rb = sB + (uint32_t)(warp_n * 64 + (g + 1) * 16 + l15) * ROWB1 + koff;
                    ldsm4(bh[nxt][0], bh[nxt][1], bh[nxt][2], bh[nxt][3], rb);
                }
                float* c00 = acc[0][2 * g];
                float* c01 = acc[0][2 * g + 1];
                float* c10 = acc[1][2 * g];
                float* c11 = acc[1][2 * g + 1];
                mma_f16(c00, a[0], bh[cur][0], bh[cur][2]);
                mma_f16(c01, a[0], bh[cur][1], bh[cur][3]);
                mma_f16(c10, a[1], bh[cur][0], bh[cur][2]);
                mma_f16(c11, a[1], bh[cur][1], bh[cur][3]);
                if (TWOPASS) {
                    mma_f16(c00, al[0], bh[cur][0], bh[cur][2]);
                    mma_f16(c01, al[0], bh[cur][1], bh[cur][3]);
                    mma_f16(c10, al[1], bh[cur][0], bh[cur][2]);
                    mma_f16(c11, al[1], bh[cur][1], bh[cur][3]);
                }
            }
        }
        __syncthreads();
    }

    #pragma unroll
    for (int mt = 0; mt < 2; ++mt) {
        #pragma unroll
        for (int h = 0; h < 2; ++h) {
            const int row = bm + warp_m * 32 + mt * 16 + (lane >> 2) + h * 8;
            #pragma unroll
            for (int nt = 0; nt < 8; ++nt) {
                const int col = bn + warp_n * 64 + nt * 8 + ((lane & 3) << 1);
                if (col < Nlimit) {
                    float t0 = tanhf(acc[mt][nt][h * 2 + 0] + bias[col]);
                    float t1 = tanhf(acc[mt][nt][h * 2 + 1] + bias[col + 1]);
                    __half2 hp;
                    hp.x = __float2half(t0);
                    hp.y = __float2half(t1);
                    *reinterpret_cast<__half2*>(outp + (size_t)row * ldo + col) = hp;
                }
            }
        }
    }
}

// ============================================================================
// Big GEMM + fused group-of-5 reduction: tile 256x160, BK=64, 3 stages, 512thr.
// w[b, m] = sum_{j5} (acc[b, m*5+j5] + bias5[m*5+j5]) * v5[b, j5]
// ============================================================================
#define W_BOFF (256 * ROWB1)            // 36864
#define W_STG  ((256 + 160) * ROWB1)    // 59904
#define W_SMEM (3 * W_STG)              // 179712
#define W_PADN 164

__global__ __launch_bounds__(512, 1)
void gemm_w(const __half* __restrict__ A, const __half* __restrict__ B,
            const float* __restrict__ bias5, const float* __restrict__ v5,
            float* __restrict__ w)
{
    extern __shared__ char smem[];
    const uint32_t sbase = smem_u32(smem);
    const int tid  = threadIdx.x;
    const int lane = tid & 31;
    const int wid  = tid >> 5;
    const int warp_m = wid & 7;           // 0..7 (32 rows each)
    const int warp_n = wid >> 3;          // 0..1 (80 cols each)
    const int bm = blockIdx.y * 256;
    const int bn = blockIdx.x * 160;

    // loader roles: threads 0..255 -> A (8 chunks), 256..511 -> B (5 chunks)
    const bool isA = tid < 256;
    const int ltid = isA ? tid : tid - 256;
    const int lrow = ltid >> 3;
    const int lcol = ltid & 7;
    const char* gsrc = isA
        ? (const char*)(A + (size_t)(bm + lrow) * CSP) + lcol * 16
        : (const char*)(B + (size_t)(bn + lrow) * CSP) + lcol * 16;
    const uint32_t dst0 = (isA ? 0u : (uint32_t)W_BOFF) + lrow * ROWB1 + lcol * 16;
    const size_t gstr = (size_t)32 * CSP * 2;   // 32 rows in bytes

    float acc[2][10][4];
    #pragma unroll
    for (int i = 0; i < 2; ++i)
        #pragma unroll
        for (int j = 0; j < 10; ++j)
            #pragma unroll
            for (int l = 0; l < 4; ++l) acc[i][j][l] = 0.f;

    auto load_stage = [&](int s, int kc) {
        const uint32_t base = sbase + s * W_STG + dst0;
        const char* g = gsrc + (size_t)kc * 128;
        if (isA) {
            #pragma unroll
            for (int t = 0; t < 8; ++t)
                cpa16(base + t * (32 * ROWB1), g + t * gstr);
        } else {
            #pragma unroll
            for (int t = 0; t < 5; ++t)
                cpa16(base + t * (32 * ROWB1), g + t * gstr);
        }
    };

    const int nk = CSP / 64;   // 104
    load_stage(0, 0); CP_COMMIT();
    load_stage(1, 1); CP_COMMIT();

    const int l15  = lane & 15;
    const int lksl = (lane >> 4) & 1;

    for (int k = 0; k < nk; ++k) {
        const int fetch = k + 2;
        if (fetch < nk) load_stage(fetch % 3, fetch);
        CP_COMMIT();
        CP_WAIT2();
        __syncthreads();

        const uint32_t sA = sbase + (k % 3) * W_STG;
        const uint32_t sB = sA + W_BOFF;

        #pragma unroll
        for (int ks = 0; ks < 4; ++ks) {
            const uint32_t koff = ks * 32 + lksl * 16;
            uint32_t a[2][4];
            #pragma unroll
            for (int mt = 0; mt < 2; ++mt) {
                uint32_t ra = sA + (uint32_t)(warp_m * 32 + mt * 16 + l15) * ROWB1 + koff;
                ldsm4(a[mt][0], a[mt][1], a[mt][2], a[mt][3], ra);
            }
            uint32_t bh[2][4];
            {
                uint32_t rb = sB + (uint32_t)(warp_n * 80 + l15) * ROWB1 + koff;
                ldsm4(bh[0][0], bh[0][1], bh[0][2], bh[0][3], rb);
            }
            #pragma unroll
            for (int g = 0; g < 5; ++g) {
                const int cur = g & 1, nxt = cur ^ 1;
                if (g < 4) {
                    uint32_t rb = sB + (uint32_t)(warp_n * 80 + (g + 1) * 16 + l15) * ROWB1 + koff;
                    ldsm4(bh[nxt][0], bh[nxt][1], bh[nxt][2], bh[nxt][3], rb);
                }
                mma_f16(acc[0][2 * g],     a[0], bh[cur][0], bh[cur][2]);
                mma_f16(acc[0][2 * g + 1], a[0], bh[cur][1], bh[cur][3]);
                mma_f16(acc[1][2 * g],     a[1], bh[cur][0], bh[cur][2]);
                mma_f16(acc[1][2 * g + 1], a[1], bh[cur][1], bh[cur][3]);
            }
        }
        __syncthreads();
    }

    // ---------------- fused epilogue: stage tile, reduce groups of 5 --------
    CP_WAIT0();
    __syncthreads();

    float* stg = reinterpret_cast<float*>(smem);          // [256][164]
    float* v5s = stg + 256 * W_PADN;                       // [256][5]
    float* b5s = v5s + 256 * 5;                            // [160]

    #pragma unroll
    for (int mt = 0; mt < 2; ++mt) {
        #pragma unroll
        for (int h = 0; h < 2; ++h) {
            const int row = warp_m * 32 + mt * 16 + (lane >> 2) + h * 8;
            #pragma unroll
            for (int nt = 0; nt < 10; ++nt) {
                const int col = warp_n * 80 + nt * 8 + ((lane & 3) << 1);
                stg[row * W_PADN + col]     = acc[mt][nt][h * 2 + 0];
                stg[row * W_PADN + col + 1] = acc[mt][nt][h * 2 + 1];
            }
        }
    }
    for (int i = tid; i < 256 * 5; i += 512) v5s[i] = v5[(size_t)bm * 5 + i];
    if (tid < 160) b5s[tid] = bias5[bn + tid];
    __syncthreads();

    const int gbase = blockIdx.x * 32;
    for (int i = tid; i < 256 * 32; i += 512) {
        const int row = i >> 5, grp = i & 31;
        const float* p  = stg + row * W_PADN + grp * 5;
        const float* vv = v5s + row * 5;
        const float* bb = b5s + grp * 5;
        float s = (p[0] + bb[0]) * vv[0];
        s = fmaf(p[1] + bb[1], vv[1], s);
        s = fmaf(p[2] + bb[2], vv[2], s);
        s = fmaf(p[3] + bb[3], vv[3], s);
        s = fmaf(p[4] + bb[4], vv[4], s);
        w[(size_t)(bm + row) * NGRP + gbase + grp] = s;
    }
}

// ---------------- transpose + fp16 (optionally compact k%6==3) --------------
__global__ __launch_bounds__(256)
void transpose_h(const float* __restrict__ W, int R, int Cstride, int nlimit,
                 __half* __restrict__ Thi, int ldt, int compact)
{
    __shared__ float ts[32][33];
    const int tx = threadIdx.x, ty = threadIdx.y;
    const int n0 = blockIdx.x * 32, k0 = blockIdx.y * 32;
    #pragma unroll
    for (int i = 0; i < 32; i += 8) {
        int k = k0 + ty + i, n = n0 + tx;
        ts[ty + i][tx] = (k < R && n < nlimit) ? W[(size_t)k * Cstride + n] : 0.f;
    }
    __syncthreads();
    #pragma unroll
    for (int i = 0; i < 32; i += 8) {
        int n = n0 + ty + i, k = k0 + tx;
        if (n < nlimit && k < R) {
            int np = n;
            if (compact) {
                int r6 = n % 6;
                if (r6 == 3) continue;
                np = (n / 6) * 5 + (r6 < 3 ? r6 : r6 - 1);
            }
            Thi[(size_t)np * ldt + k] = __float2half(ts[tx][ty + i]);
        }
    }
}

// ---------------- gather W3 tail cols + bias5 --------------------------------
__global__ __launch_bounds__(256)
void gather_tail(const float* __restrict__ W3, const float* __restrict__ b3,
                 float* __restrict__ w3t12, float* __restrict__ bias5)
{
    int i = blockIdx.x * 256 + threadIdx.x;
    if (i < CS * 12) {
        int c = i / 12, j = i % 12;
        w3t12[(size_t)j * CSP + c] = W3[(size_t)c * CS + MK + j];
    }
    if (i < MK5) {
        int m6 = i / 5, j5 = i - m6 * 5;
        int kk = (j5 < 3) ? j5 : j5 + 1;
        bias5[i] = b3[m6 * 6 + kk];
    }
}

// ---------------- z -> fp16 hi/lo (contiguous [B][128]) ---------------------
__global__ __launch_bounds__(256)
void zprep(const float* __restrict__ x, __half* __restrict__ zhi, __half* __restrict__ zlo)
{
    int i = blockIdx.x * 256 + threadIdx.x;
    if (i < B_SZ * LAT) {
        int b = i >> 7, c = i & 127;
        float v = x[(size_t)b * XCOLS + (IN_F + 1) + c];
        __half h = __float2half(v);
        zhi[i] = h;
        zlo[i] = __float2half(v - __half2float(h));
    }
}

// ---------------- tail GEMM: 32 rows/block, 8 thr/row, shfl reduce ----------
__global__ __launch_bounds__(256)
void tail_gemm(const __half* __restrict__ h2h,
               const float* __restrict__ w3t12,
               const float* __restrict__ b3,
               const float* __restrict__ x,
               float* __restrict__ v5)
{
    __shared__ __half h2s[32 * 72];
    __shared__ float  w3s[64 * 12];

    const int tid = threadIdx.x;
    const int bm = blockIdx.x * 32;
    const int row_l = tid >> 3;       // 0..31
    const int ksub = tid & 7;

    float acc[12];
    #pragma unroll
    for (int j = 0; j < 12; ++j) acc[j] = 0.f;

    for (int kc = 0; kc < CSP / 64; ++kc) {
        {
            uint4 v = *reinterpret_cast<const uint4*>(
                h2h + (size_t)(bm + row_l) * CSP + kc * 64 + ksub * 8);
            *reinterpret_cast<uint4*>(&h2s[row_l * 72 + ksub * 8]) = v;
        }
        for (int i = tid; i < 64 * 12; i += 256) {
            int k = i / 12, j = i % 12;
            w3s[i] = w3t12[(size_t)j * CSP + kc * 64 + k];
        }
        __syncthreads();

        #pragma unroll
        for (int kk = 0; kk < 8; ++kk) {
            int k = kk * 8 + ksub;
            float hv = __half2float(h2s[row_l * 72 + k]);
            #pragma unroll
            for (int j = 0; j < 12; ++j)
                acc[j] = fmaf(hv, w3s[k * 12 + j], acc[j]);
        }
        __syncthreads();
    }

    // reduce across the 8 threads of each row (consecutive lanes)
    #pragma unroll
    for (int j = 0; j < 12; ++j) {
        #pragma unroll
        for (int d = 4; d > 0; d >>= 1)
            acc[j] += __shfl_down_sync(0xffffffffu, acc[j], d);
    }

    if (ksub == 0) {
        float s = x[(size_t)(B_SZ - 1) * XCOLS + IN_F];
        float dt[12];
        #pragma unroll
        for (int j = 0; j < 12; ++j) dt[j] = acc[j] + b3[MK + j];
        #pragma unroll
        for (int t5 = 0; t5 < 5; ++t5) {
            int k = (t5 < 3) ? t5 : t5 + 1;
            float sv = fmaf(s, dt[k], dt[k + 6]);
            float r = (k < 3) ? cosf(sv * (float)k) : sinf(sv * (float)(k - 3));
            v5[(size_t)(bm + row_l) * 5 + t5] = r;
        }
    }
}

// ---------------- final: out[b,o] = sum_i inp[b,i]*w[b,i*64+o] + w[b,1024+o] -
__global__ __launch_bounds__(256)
void final_kernel(const float* __restrict__ w,
                  const float* __restrict__ x,
                  float* __restrict__ out)
{
    __shared__ float inp[4][IN_F];
    const int tid = threadIdx.x;
    const int b0 = blockIdx.x * 4;
    if (tid < 4 * IN_F)
        inp[tid >> 4][tid & 15] = x[(size_t)(b0 + (tid >> 4)) * XCOLS + (tid & 15)];
    __syncthreads();

    const int r = tid >> 6;           // 0..3
    const int o = tid & 63;
    const int b = b0 + r;
    const float* wr = w + (size_t)b * NGRP;
    float accum = wr[1024 + o];
    #pragma unroll
    for (int i = 0; i < IN_F; ++i)
        accum = fmaf(inp[r][i], wr[i * 64 + o], accum);
    out[(size_t)b * 64 + o] = accum;
}

// ----------------------------- launch ---------------------------------------
extern "C" void kernel_launch(void* const* d_in, const int* in_sizes, int n_in,
                              void* d_out, int out_size)
{
    const float* x  = (const float*)d_in[0];
    const float* W1 = (const float*)d_in[1];
    const float* b1 = (const float*)d_in[2];
    const float* W2 = (const float*)d_in[3];
    const float* b2 = (const float*)d_in[4];
    const float* W3 = (const float*)d_in[5];
    const float* b3 = (const float*)d_in[6];
    float* out = (float*)d_out;

    __half *zhi, *zlo, *w1t, *h1h, *h2h, *w2th, *w3th;
    float *w3t12, *bias5, *wbuf, *v5;
    cudaGetSymbolAddress((void**)&zhi,  g_zhi);
    cudaGetSymbolAddress((void**)&zlo,  g_zlo);
    cudaGetSymbolAddress((void**)&w1t,  g_w1t);
    cudaGetSymbolAddress((void**)&h1h,  g_h1h);
    cudaGetSymbolAddress((void**)&h2h,  g_h2h);
    cudaGetSymbolAddress((void**)&w2th, g_w2th);
    cudaGetSymbolAddress((void**)&w3th, g_w3th);
    cudaGetSymbolAddress((void**)&w3t12, g_w3t12);
    cudaGetSymbolAddress((void**)&bias5, g_bias5);
    cudaGetSymbolAddress((void**)&wbuf, g_w);
    cudaGetSymbolAddress((void**)&v5,  g_v5);

    const int SM_2P = 3 * 384 * ROWB1;   // 165888
    const int SM_1P = 3 * 256 * ROWB1;   // 110592

    static bool attr_set = false;
    if (!attr_set) {
        cudaFuncSetAttribute(gemm_f16<1>, cudaFuncAttributeMaxDynamicSharedMemorySize, SM_2P);
        cudaFuncSetAttribute(gemm_f16<0>, cudaFuncAttributeMaxDynamicSharedMemorySize, SM_1P);
        cudaFuncSetAttribute(gemm_w, cudaFuncAttributeMaxDynamicSharedMemorySize, W_SMEM);
        attr_set = true;
    }

    // 0) prep
    transpose_h<<<dim3((CS + 31) / 32, (HID + 31) / 32), dim3(32, 8)>>>(
        W2, HID, CS, CS, w2th, HID, 0);
    transpose_h<<<dim3((MK + 31) / 32, (CS + 31) / 32), dim3(32, 8)>>>(
        W3, CS, CS, MK, w3th, CSP, 1);
    transpose_h<<<dim3((HID + 31) / 32, (LAT + 31) / 32), dim3(32, 8)>>>(
        W1, LAT, HID, HID, w1t, LAT, 0);
    gather_tail<<<(CS * 12 + 255) / 256, 256>>>(W3, b3, w3t12, bias5);
    zprep<<<(B_SZ * LAT + 255) / 256, 256>>>(x, zhi, zlo);

    // 1) h1 = tanh(z @ W1 + b1): 2-pass (exact z), K=128
    gemm_f16<1><<<dim3(HID / 128, B_SZ / 128), 256, SM_2P>>>(
        zhi, zlo, LAT, w1t, LAT, LAT / 64, b1, h1h, HID, HID);

    // 2) h2 = tanh(h1 @ W2 + b2): 1-pass, K=1024
    gemm_f16<0><<<dim3(CSP / 128, B_SZ / 128), 256, SM_1P>>>(
        h1h, nullptr, HID, w2th, HID, HID / 64, b2, h2h, CSP, CS);

    // 3) tail mini-GEMM -> v5 (256 blocks)
    tail_gemm<<<B_SZ / 32, 256>>>(h2h, w3t12, b3, x, v5);

    // 4) big GEMM + fused group-of-5 reduction -> w[B][1088]
    gemm_w<<<dim3(MK5 / 160, B_SZ / 256), 512, W_SMEM>>>(
        h2h, w3th, bias5, v5, wbuf);

    // 5) adaptive 16->64 linear from fused weights
    final_kernel<<<B_SZ / 4, 256>>>(wbuf, x, out);
}